// round 3
// baseline (speedup 1.0000x reference)
#include <cuda_runtime.h>
#include <math.h>

#define BSZ   32768
#define OBS   1024
#define OUTD  256
#define KCB   512
#define HENCD 1024

#define LOG2PI_F 1.83787706640934534f

// ---------------- scratch (device globals; no allocation allowed) -------------
__device__ float g_cbT[OBS * KCB];          // codebook transposed [D, K]
__device__ float g_cnorm[KCB];
__device__ float g_xnorm[BSZ];
__device__ float g_h1[(size_t)BSZ * 512];
__device__ float g_h2[(size_t)BSZ * 1024];
__device__ float g_enc[(size_t)BSZ * 1024];
__device__ float g_dist[(size_t)BSZ * 512];
__device__ int   g_prop[BSZ];
__device__ float g_quant[(size_t)BSZ * 1024];
__device__ float g_d0[(size_t)BSZ * 1024];
__device__ float g_d1[(size_t)BSZ * 2048];
__device__ float g_d2[(size_t)BSZ * 2048];
__device__ float g_recon[(size_t)BSZ * 1024];
__device__ float g_cs[(size_t)BSZ * 1536];
__device__ float g_a1[(size_t)BSZ * 2048];
__device__ float g_a2[(size_t)BSZ * 2048];
__device__ float g_mu[(size_t)BSZ * 256];
__device__ float g_part[2048 * 2];
__device__ float g_total[1];

// ---------------- packed f32x2 helpers (Blackwell FFMA2 path) ------------------
__device__ __forceinline__ unsigned long long pack2_bcast(float x) {
    unsigned long long r;
    asm("mov.b64 %0, {%1, %1};" : "=l"(r) : "f"(x));
    return r;
}
__device__ __forceinline__ void ffma2(unsigned long long& d, unsigned long long a,
                                      unsigned long long b) {
    asm("fma.rn.f32x2 %0, %1, %2, %0;" : "+l"(d) : "l"(a), "l"(b));
}
__device__ __forceinline__ float2 unpack2(unsigned long long v) {
    float2 f;
    asm("mov.b64 {%0, %1}, %2;" : "=f"(f.x), "=f"(f.y) : "l"(v));
    return f;
}

// ---------------- helpers ------------------------------------------------------
__device__ __forceinline__ float blockReduceSum(float v) {
    __shared__ float sh[32];
    int lane = threadIdx.x & 31, wid = threadIdx.x >> 5;
#pragma unroll
    for (int o = 16; o > 0; o >>= 1) v += __shfl_down_sync(0xffffffffu, v, o);
    if (lane == 0) sh[wid] = v;
    __syncthreads();
    int nw = blockDim.x >> 5;
    v = (threadIdx.x < nw) ? sh[threadIdx.x] : 0.f;
    if (wid == 0) {
#pragma unroll
        for (int o = 16; o > 0; o >>= 1) v += __shfl_down_sync(0xffffffffu, v, o);
    }
    __syncthreads();
    return v;  // valid on thread 0
}

// ---------------- SGEMM: C[M,N] = epi(A[M,K] @ B[K,N]) -------------------------
// EPI 0: acc + bias[n]
// EPI 1: tanh(acc + bias[n])
// EPI 2: rown[m] + bias[n] - 2*acc        (squared-distance epilogue)
#define BM 128
#define BN 128
#define BK 8

template <int EPI>
__global__ void __launch_bounds__(256)
sgemm_kernel(const float* __restrict__ A, const float* __restrict__ B,
             const float* __restrict__ bias, const float* __restrict__ rown,
             float* __restrict__ C, int M, int N, int K) {
    __shared__ __align__(16) float As[2][BK][BM];
    __shared__ __align__(16) float Bs[2][BK][BN];

    const int tid = threadIdx.x;
    const int tx = tid & 15;   // 0..15
    const int ty = tid >> 4;   // 0..15
    const int m0 = blockIdx.y * BM;
    const int n0 = blockIdx.x * BN;

    const int arow = tid >> 1;
    const int akq = (tid & 1) * 4;
    const float* Aptr = A + (size_t)(m0 + arow) * K + akq;

    const int brow = tid >> 5;          // 0..7
    const int bcol = (tid & 31) * 4;    // 0..124
    const float* Bptr = B + (size_t)brow * N + n0 + bcol;

    // accumulators: 8 rows x 4 packed column-pairs (64 fp32 lanes)
    unsigned long long acc2[8][4];
#pragma unroll
    for (int i = 0; i < 8; i++)
#pragma unroll
        for (int j = 0; j < 4; j++) acc2[i][j] = 0ull;

    const int nt = K / BK;

    float4 a4 = *(const float4*)(Aptr);
    float4 b4 = *(const float4*)(Bptr);
    As[0][akq + 0][arow] = a4.x; As[0][akq + 1][arow] = a4.y;
    As[0][akq + 2][arow] = a4.z; As[0][akq + 3][arow] = a4.w;
    *(float4*)&Bs[0][brow][bcol] = b4;
    __syncthreads();

    int cur = 0;
    for (int t = 0; t < nt; t++) {
        if (t + 1 < nt) {
            a4 = *(const float4*)(Aptr + (t + 1) * BK);
            b4 = *(const float4*)(Bptr + (size_t)(t + 1) * BK * N);
        }
#pragma unroll
        for (int kk = 0; kk < BK; kk++) {
            float4 a0 = *(const float4*)&As[cur][kk][ty * 4];
            float4 a1 = *(const float4*)&As[cur][kk][64 + ty * 4];
            // B pairs come out of LDS.128 already packed as register pairs
            ulonglong2 bq0 = *(const ulonglong2*)&Bs[cur][kk][tx * 4];
            ulonglong2 bq1 = *(const ulonglong2*)&Bs[cur][kk][64 + tx * 4];
            unsigned long long bb[4] = {bq0.x, bq0.y, bq1.x, bq1.y};
            float ar[8] = {a0.x, a0.y, a0.z, a0.w, a1.x, a1.y, a1.z, a1.w};
#pragma unroll
            for (int i = 0; i < 8; i++) {
                unsigned long long aa = pack2_bcast(ar[i]);
#pragma unroll
                for (int j = 0; j < 4; j++) ffma2(acc2[i][j], aa, bb[j]);
            }
        }
        if (t + 1 < nt) {
            int nx = cur ^ 1;
            As[nx][akq + 0][arow] = a4.x; As[nx][akq + 1][arow] = a4.y;
            As[nx][akq + 2][arow] = a4.z; As[nx][akq + 3][arow] = a4.w;
            *(float4*)&Bs[nx][brow][bcol] = b4;
        }
        __syncthreads();
        cur ^= 1;
    }

#pragma unroll
    for (int i = 0; i < 8; i++) {
        int r = m0 + ((i < 4) ? (ty * 4 + i) : (64 + ty * 4 + (i - 4)));
        float rn = (EPI == 2) ? rown[r] : 0.f;
#pragma unroll
        for (int jh = 0; jh < 2; jh++) {
            int c = n0 + jh * 64 + tx * 4;
            float4 bv = *(const float4*)(bias + c);
            float2 p0 = unpack2(acc2[i][jh * 2 + 0]);
            float2 p1 = unpack2(acc2[i][jh * 2 + 1]);
            float ap[4] = {p0.x, p0.y, p1.x, p1.y};
            float4 v;
            if (EPI == 2) {
                v.x = rn + bv.x - 2.f * ap[0];
                v.y = rn + bv.y - 2.f * ap[1];
                v.z = rn + bv.z - 2.f * ap[2];
                v.w = rn + bv.w - 2.f * ap[3];
            } else {
                v.x = ap[0] + bv.x; v.y = ap[1] + bv.y;
                v.z = ap[2] + bv.z; v.w = ap[3] + bv.w;
                if (EPI == 1) {
                    v.x = tanhf(v.x); v.y = tanhf(v.y);
                    v.z = tanhf(v.z); v.w = tanhf(v.w);
                }
            }
            *(float4*)(C + (size_t)r * N + c) = v;
        }
    }
}

// ---------------- small kernels -------------------------------------------------
__global__ void prep_codebook_kernel(const float* __restrict__ cb) {
    int k = blockIdx.x;  // 0..KCB-1
    float s = 0.f;
    for (int d = threadIdx.x; d < OBS; d += blockDim.x) {
        float v = cb[(size_t)k * OBS + d];
        g_cbT[(size_t)d * KCB + k] = v;
        s += v * v;
    }
    s = blockReduceSum(s);
    if (threadIdx.x == 0) g_cnorm[k] = s;
}

__global__ void rownorm_kernel(const float* __restrict__ x, float* __restrict__ out, int D) {
    int b = blockIdx.x;
    const float* r = x + (size_t)b * D;
    float s = 0.f;
    for (int d = threadIdx.x; d < D; d += blockDim.x) {
        float v = r[d];
        s += v * v;
    }
    s = blockReduceSum(s);
    if (threadIdx.x == 0) out[b] = s;
}

__global__ void argmin_kernel(const float* __restrict__ dist, float* __restrict__ prop_out_f) {
    __shared__ float sv[256];
    __shared__ int si[256];
    int b = blockIdx.x;
    const float* r = dist + (size_t)b * KCB;
    float best = INFINITY;
    int bi = KCB;
    for (int k = threadIdx.x; k < KCB; k += 256) {
        float v = r[k];
        if (v < best) { best = v; bi = k; }
    }
    sv[threadIdx.x] = best;
    si[threadIdx.x] = bi;
    __syncthreads();
    for (int s = 128; s > 0; s >>= 1) {
        if (threadIdx.x < s) {
            float ov = sv[threadIdx.x + s];
            int oi = si[threadIdx.x + s];
            if (ov < sv[threadIdx.x] || (ov == sv[threadIdx.x] && oi < si[threadIdx.x])) {
                sv[threadIdx.x] = ov;
                si[threadIdx.x] = oi;
            }
        }
        __syncthreads();
    }
    if (threadIdx.x == 0) {
        g_prop[b] = si[0];
        prop_out_f[b] = (float)si[0];
    }
}

__global__ void gather_kernel(const float* __restrict__ cb) {
    size_t i = (size_t)blockIdx.x * blockDim.x + threadIdx.x;  // B*OBS threads
    int b = (int)(i >> 10);
    int d = (int)(i & 1023);
    g_quant[i] = cb[(size_t)g_prop[b] * OBS + d];
}

__global__ void concat_kernel(const float* __restrict__ X) {
    size_t i = (size_t)blockIdx.x * blockDim.x + threadIdx.x;  // B*1536 threads
    int b = (int)(i / 1536);
    int j = (int)(i % 1536);
    g_cs[i] = (j < OBS) ? X[(size_t)b * OBS + j] : g_dist[(size_t)b * KCB + (j - OBS)];
}

__global__ void loss_partial_kernel(const float* __restrict__ dx) {
    const size_t NTOT = (size_t)BSZ * OBS;
    float s1 = 0.f, s2 = 0.f;
    for (size_t i = (size_t)blockIdx.x * blockDim.x + threadIdx.x; i < NTOT;
         i += (size_t)gridDim.x * blockDim.x) {
        float a = dx[i] - g_recon[i];
        s1 += a * a;
        float c = g_enc[i] - g_quant[i];
        s2 += c * c;
    }
    s1 = blockReduceSum(s1);
    __syncthreads();
    s2 = blockReduceSum(s2);
    if (threadIdx.x == 0) {
        g_part[2 * blockIdx.x + 0] = s1;
        g_part[2 * blockIdx.x + 1] = s2;
    }
}

__global__ void finalize_total_kernel(int nb, float* __restrict__ out_total) {
    float s1 = 0.f, s2 = 0.f;
    for (int i = threadIdx.x; i < nb; i += 256) {
        s1 += g_part[2 * i + 0];
        s2 += g_part[2 * i + 1];
    }
    s1 = blockReduceSum(s1);
    __syncthreads();
    s2 = blockReduceSum(s2);
    if (threadIdx.x == 0) {
        const float inv = 1.f / ((float)BSZ * (float)OBS);
        float tot = s1 * inv + 2.f * (s2 * inv);  // recon + vq + commit (KL_BETA=1)
        g_total[0] = tot;
        out_total[0] = tot;
    }
}

__global__ void policy_kernel(const float* __restrict__ A_, const float* __restrict__ log_std,
                              float* __restrict__ out_loss, float* __restrict__ out_losspi) {
    int b = blockIdx.x;
    int j = threadIdx.x;  // 256 threads == OUTD
    float ls = log_std[j];
    float sd = expf(ls);
    float z = (A_[(size_t)b * OUTD + j] - g_mu[(size_t)b * OUTD + j]) / sd;
    float logp = -0.5f * z * z - ls - 0.5f * LOG2PI_F;
    float term = 1.f / (expf(logp) + 0.1f);
    float lp = blockReduceSum(term);
    if (threadIdx.x == 0) {
        out_losspi[b] = lp;
        out_loss[b] = lp * g_total[0];
    }
}

// ---------------- launch -------------------------------------------------------
static inline dim3 gemm_grid(int M, int N) { return dim3(N / BN, M / BM); }

extern "C" void kernel_launch(void* const* d_in, const int* in_sizes, int n_in,
                              void* d_out, int out_size) {
    const float* X        = (const float*)d_in[0];
    const float* Delta_X  = (const float*)d_in[1];
    const float* A        = (const float*)d_in[2];
    const float* enc_w1   = (const float*)d_in[3];
    const float* enc_b1   = (const float*)d_in[4];
    const float* enc_w2   = (const float*)d_in[5];
    const float* enc_b2   = (const float*)d_in[6];
    const float* prenet_w = (const float*)d_in[7];
    const float* prenet_b = (const float*)d_in[8];
    const float* codebook = (const float*)d_in[9];
    const float* postnet_w= (const float*)d_in[10];
    const float* postnet_b= (const float*)d_in[11];
    const float* dec_w1   = (const float*)d_in[12];
    const float* dec_b1   = (const float*)d_in[13];
    const float* dec_w2   = (const float*)d_in[14];
    const float* dec_b2   = (const float*)d_in[15];
    const float* dec_w3   = (const float*)d_in[16];
    const float* dec_b3   = (const float*)d_in[17];
    const float* act_w1   = (const float*)d_in[18];
    const float* act_b1   = (const float*)d_in[19];
    const float* act_w2   = (const float*)d_in[20];
    const float* act_b2   = (const float*)d_in[21];
    const float* act_w3   = (const float*)d_in[22];
    const float* act_b3   = (const float*)d_in[23];
    const float* log_std  = (const float*)d_in[24];

    float* out = (float*)d_out;
    float* out_loss   = out;                       // [B]
    float* out_losspi = out + BSZ;                 // [B]
    float* out_X      = out + 2 * (size_t)BSZ;     // [B, OBS]
    float* out_prop   = out + 2 * (size_t)BSZ + (size_t)BSZ * OBS;  // [B]
    float* out_total  = out_prop + BSZ;            // [1]

    float *p_h1, *p_h2, *p_enc, *p_dist, *p_quant, *p_d0, *p_d1, *p_d2, *p_recon,
          *p_cs, *p_a1, *p_a2, *p_mu, *p_cbT, *p_cnorm, *p_xnorm;
    cudaGetSymbolAddress((void**)&p_h1, g_h1);
    cudaGetSymbolAddress((void**)&p_h2, g_h2);
    cudaGetSymbolAddress((void**)&p_enc, g_enc);
    cudaGetSymbolAddress((void**)&p_dist, g_dist);
    cudaGetSymbolAddress((void**)&p_quant, g_quant);
    cudaGetSymbolAddress((void**)&p_d0, g_d0);
    cudaGetSymbolAddress((void**)&p_d1, g_d1);
    cudaGetSymbolAddress((void**)&p_d2, g_d2);
    cudaGetSymbolAddress((void**)&p_recon, g_recon);
    cudaGetSymbolAddress((void**)&p_cs, g_cs);
    cudaGetSymbolAddress((void**)&p_a1, g_a1);
    cudaGetSymbolAddress((void**)&p_a2, g_a2);
    cudaGetSymbolAddress((void**)&p_mu, g_mu);
    cudaGetSymbolAddress((void**)&p_cbT, g_cbT);
    cudaGetSymbolAddress((void**)&p_cnorm, g_cnorm);
    cudaGetSymbolAddress((void**)&p_xnorm, g_xnorm);

    // 0. codebook transpose + norms
    prep_codebook_kernel<<<KCB, 256>>>(codebook);

    // 1-3. VQ encoder
    sgemm_kernel<1><<<gemm_grid(BSZ, 512), 256>>>(Delta_X, enc_w1, enc_b1, nullptr, p_h1, BSZ, 512, 1024);
    sgemm_kernel<1><<<gemm_grid(BSZ, 1024), 256>>>(p_h1, enc_w2, enc_b2, nullptr, p_h2, BSZ, 1024, 512);
    sgemm_kernel<0><<<gemm_grid(BSZ, 1024), 256>>>(p_h2, prenet_w, prenet_b, nullptr, p_enc, BSZ, 1024, 1024);

    // 4-6. distances + argmin + gather
    rownorm_kernel<<<BSZ, 256>>>(p_enc, p_xnorm, OBS);
    sgemm_kernel<2><<<gemm_grid(BSZ, KCB), 256>>>(p_enc, p_cbT, p_cnorm, p_xnorm, p_dist, BSZ, KCB, OBS);
    argmin_kernel<<<BSZ, 256>>>(p_dist, out_prop);
    gather_kernel<<<(BSZ * OBS) / 256, 256>>>(codebook);

    // 7-10. postnet + decoder (forward st_q == quantized)
    sgemm_kernel<1><<<gemm_grid(BSZ, HENCD), 256>>>(p_quant, postnet_w, postnet_b, nullptr, p_d0, BSZ, HENCD, 1024);
    sgemm_kernel<1><<<gemm_grid(BSZ, 2048), 256>>>(p_d0, dec_w1, dec_b1, nullptr, p_d1, BSZ, 2048, 1024);
    sgemm_kernel<1><<<gemm_grid(BSZ, 2048), 256>>>(p_d1, dec_w2, dec_b2, nullptr, p_d2, BSZ, 2048, 2048);
    sgemm_kernel<0><<<gemm_grid(BSZ, 1024), 256>>>(p_d2, dec_w3, dec_b3, nullptr, p_recon, BSZ, 1024, 2048);

    // 11-14. actor
    concat_kernel<<<((size_t)BSZ * 1536) / 256, 256>>>(X);
    sgemm_kernel<1><<<gemm_grid(BSZ, 2048), 256>>>(p_cs, act_w1, act_b1, nullptr, p_a1, BSZ, 2048, 1536);
    sgemm_kernel<1><<<gemm_grid(BSZ, 2048), 256>>>(p_a1, act_w2, act_b2, nullptr, p_a2, BSZ, 2048, 2048);
    sgemm_kernel<0><<<gemm_grid(BSZ, 256), 256>>>(p_a2, act_w3, act_b3, nullptr, p_mu, BSZ, 256, 2048);

    // 15-17. losses
    loss_partial_kernel<<<2048, 256>>>(Delta_X);
    finalize_total_kernel<<<1, 256>>>(2048, out_total);
    policy_kernel<<<BSZ, 256>>>(A, log_std, out_loss, out_losspi);

    // 18. X pass-through
    cudaMemcpyAsync(out_X, X, (size_t)BSZ * OBS * sizeof(float),
                    cudaMemcpyDeviceToDevice);
}

// round 5
// speedup vs baseline: 1.3741x; 1.3741x over previous
#include <cuda_runtime.h>
#include <cuda_bf16.h>
#include <math.h>
#include <stdint.h>

#define BSZ   32768
#define OBS   1024
#define OUTD  256
#define KCB   512
#define LOG2PI_F 1.83787706640934534f

// ---------------- fp32 scratch ---------------------------------------------------
__device__ float g_cbT[OBS * KCB];
__device__ float g_cnorm[KCB];
__device__ float g_xnorm[BSZ];
__device__ float g_h1[(size_t)BSZ * 512];
__device__ float g_h2[(size_t)BSZ * 1024];
__device__ float g_enc[(size_t)BSZ * 1024];
__device__ float g_dist[(size_t)BSZ * 512];
__device__ int   g_prop[BSZ];
__device__ float g_quant[(size_t)BSZ * 1024];
__device__ float g_recon[(size_t)BSZ * 1024];
__device__ float g_mu[(size_t)BSZ * 256];
__device__ float g_part[2048 * 2];
__device__ float g_total[1];

// ---------------- bf16 split activation arena -------------------------------------
#define AO_QNT 0ull
#define AO_D0  ((size_t)BSZ * 1024)
#define AO_D1  (AO_D0 + (size_t)BSZ * 1024)
#define AO_D2  (AO_D1 + (size_t)BSZ * 2048)
#define AO_CS  (AO_D2 + (size_t)BSZ * 2048)
#define AO_A1  (AO_CS + (size_t)BSZ * 1536)
#define AO_A2  (AO_A1 + (size_t)BSZ * 2048)
#define AO_TOT (AO_A2 + (size_t)BSZ * 2048)
__device__ __nv_bfloat16 g_act_hi[AO_TOT];
__device__ __nv_bfloat16 g_act_lo[AO_TOT];

// transposed + split weights [N][K] bf16 (tensor-core GEMMs only)
#define O_POST  0u
#define O_DEC1  1048576u
#define O_DEC2  3145728u
#define O_DEC3  7340032u
#define O_ACT1  9437184u
#define O_ACT2  12582912u
#define O_ACT3  16777216u
#define WT_TOTAL 17301504u
__device__ __nv_bfloat16 g_wt_hi[WT_TOTAL];
__device__ __nv_bfloat16 g_wt_lo[WT_TOTAL];

// ---------------- small helpers ----------------------------------------------------
__device__ __forceinline__ uint32_t smem_u32(const void* p) {
    uint32_t a;
    asm("{ .reg .u64 t; cvta.to.shared.u64 t, %1; cvt.u32.u64 %0, t; }" : "=r"(a) : "l"(p));
    return a;
}
__device__ __forceinline__ void cp16(uint32_t sdst, const void* gsrc) {
    uint64_t g;
    asm("cvta.to.global.u64 %0, %1;" : "=l"(g) : "l"(gsrc));
    asm volatile("cp.async.cg.shared.global [%0], [%1], 16;" :: "r"(sdst), "l"(g) : "memory");
}
__device__ __forceinline__ void cp_commit() {
    asm volatile("cp.async.commit_group;" ::: "memory");
}
template <int N>
__device__ __forceinline__ void cp_wait() {
    asm volatile("cp.async.wait_group %0;" :: "n"(N) : "memory");
}
__device__ __forceinline__ void ldsm4(uint32_t& r0, uint32_t& r1, uint32_t& r2, uint32_t& r3,
                                      uint32_t a) {
    asm volatile("ldmatrix.sync.aligned.m8n8.x4.shared.b16 {%0,%1,%2,%3}, [%4];"
                 : "=r"(r0), "=r"(r1), "=r"(r2), "=r"(r3) : "r"(a));
}
__device__ __forceinline__ void mma16816(float* c, const uint32_t* a, const uint32_t* b) {
    asm volatile("mma.sync.aligned.m16n8k16.row.col.f32.bf16.bf16.f32 "
                 "{%0,%1,%2,%3}, {%4,%5,%6,%7}, {%8,%9}, {%0,%1,%2,%3};"
                 : "+f"(c[0]), "+f"(c[1]), "+f"(c[2]), "+f"(c[3])
                 : "r"(a[0]), "r"(a[1]), "r"(a[2]), "r"(a[3]), "r"(b[0]), "r"(b[1]));
}
__device__ __forceinline__ void split2(float v, __nv_bfloat16& h, __nv_bfloat16& l) {
    h = __float2bfloat16(v);
    l = __float2bfloat16(v - __bfloat162float(h));
}

// ---------------- tensor-core GEMM: C[M,N] = epi(A @ W[N,K]^T) ---------------------
// A given as pre-split bf16 hi/lo [M,K]; W pre-split [N,K].
// EPI 1 -> tanh(acc+bias), EPI 0 -> acc+bias. WF32: write fp32 C. WSPLIT: write hi/lo C.
#define PITCH 40           // bf16 elems per smem row (32 data + 8 pad)
#define ST_A_H 0
#define ST_A_L 5120
#define ST_B_H 10240
#define ST_B_L 15360
#define ST_STRIDE 20480    // bf16 elems per stage
#define STAGES 3
#define GEMM_SMEM (STAGES * ST_STRIDE * 2)

template <int EPI, int WF32, int WSPLIT>
__global__ void __launch_bounds__(256, 1)
mma_gemm(const __nv_bfloat16* __restrict__ Ah, const __nv_bfloat16* __restrict__ Al,
         const __nv_bfloat16* __restrict__ Wh, const __nv_bfloat16* __restrict__ Wl,
         const float* __restrict__ bias, float* __restrict__ Cf,
         __nv_bfloat16* __restrict__ Ch, __nv_bfloat16* __restrict__ Cl,
         int M, int N, int K) {
    extern __shared__ __nv_bfloat16 sm[];
    __shared__ float s_bias[128];
    const int tid = threadIdx.x;
    const int lane = tid & 31, wid = tid >> 5;
    const int wm = wid >> 2, wn = wid & 3;          // 2 x 4 warp grid, 64m x 32n each
    const int m0 = blockIdx.y * 128, n0 = blockIdx.x * 128;
    const uint32_t smb = smem_u32(sm);

    if (tid < 128) s_bias[tid] = bias[n0 + tid];

    const int crow = tid >> 1;
    const int ck = (tid & 1) * 16;
    const __nv_bfloat16* gAh = Ah + (size_t)(m0 + crow) * K + ck;
    const __nv_bfloat16* gAl = Al + (size_t)(m0 + crow) * K + ck;
    const __nv_bfloat16* gWh = Wh + (size_t)(n0 + crow) * K + ck;
    const __nv_bfloat16* gWl = Wl + (size_t)(n0 + crow) * K + ck;
    const uint32_t srow = (uint32_t)(crow * PITCH + ck) * 2;

    const int nk = K >> 5;

#pragma unroll
    for (int s = 0; s < STAGES - 1; ++s) {
        uint32_t sb = smb + (uint32_t)s * (ST_STRIDE * 2);
        int kk = s * 32;
        cp16(sb + ST_A_H * 2 + srow,      gAh + kk);
        cp16(sb + ST_A_H * 2 + srow + 16, gAh + kk + 8);
        cp16(sb + ST_A_L * 2 + srow,      gAl + kk);
        cp16(sb + ST_A_L * 2 + srow + 16, gAl + kk + 8);
        cp16(sb + ST_B_H * 2 + srow,      gWh + kk);
        cp16(sb + ST_B_H * 2 + srow + 16, gWh + kk + 8);
        cp16(sb + ST_B_L * 2 + srow,      gWl + kk);
        cp16(sb + ST_B_L * 2 + srow + 16, gWl + kk + 8);
        cp_commit();
    }

    float acc[4][4][4];
#pragma unroll
    for (int i = 0; i < 4; i++)
#pragma unroll
        for (int j = 0; j < 4; j++)
#pragma unroll
            for (int q = 0; q < 4; q++) acc[i][j][q] = 0.f;

    const int fr = lane & 15;
    const int fc = (lane >> 4) << 3;

    for (int t = 0; t < nk; ++t) {
        cp_wait<STAGES - 2>();
        __syncthreads();
        uint32_t sb = smb + (uint32_t)(t % STAGES) * (ST_STRIDE * 2);
#pragma unroll
        for (int ks = 0; ks < 2; ++ks) {
            uint32_t ah[4][4], al[4][4], bh[4][2], bl[4][2];
#pragma unroll
            for (int mt = 0; mt < 4; ++mt) {
                uint32_t a = sb + ST_A_H * 2 +
                             (uint32_t)((wm * 64 + mt * 16 + fr) * PITCH + ks * 16 + fc) * 2;
                ldsm4(ah[mt][0], ah[mt][1], ah[mt][2], ah[mt][3], a);
                ldsm4(al[mt][0], al[mt][1], al[mt][2], al[mt][3],
                      a + (ST_A_L - ST_A_H) * 2);
            }
#pragma unroll
            for (int pn = 0; pn < 2; ++pn) {
                uint32_t a = sb + ST_B_H * 2 +
                             (uint32_t)((wn * 32 + pn * 16 + fr) * PITCH + ks * 16 + fc) * 2;
                uint32_t r0, r1, r2, r3;
                ldsm4(r0, r1, r2, r3, a);
                bh[pn * 2][0] = r0; bh[pn * 2][1] = r2;
                bh[pn * 2 + 1][0] = r1; bh[pn * 2 + 1][1] = r3;
                ldsm4(r0, r1, r2, r3, a + (ST_B_L - ST_B_H) * 2);
                bl[pn * 2][0] = r0; bl[pn * 2][1] = r2;
                bl[pn * 2 + 1][0] = r1; bl[pn * 2 + 1][1] = r3;
            }
#pragma unroll
            for (int mt = 0; mt < 4; ++mt)
#pragma unroll
                for (int nt = 0; nt < 4; ++nt) {
                    mma16816(acc[mt][nt], ah[mt], bh[nt]);
                    mma16816(acc[mt][nt], ah[mt], bl[nt]);
                    mma16816(acc[mt][nt], al[mt], bh[nt]);
                }
        }
        __syncthreads();
        int tn = t + STAGES - 1;
        if (tn < nk) {
            uint32_t sb2 = smb + (uint32_t)(tn % STAGES) * (ST_STRIDE * 2);
            int kk = tn * 32;
            cp16(sb2 + ST_A_H * 2 + srow,      gAh + kk);
            cp16(sb2 + ST_A_H * 2 + srow + 16, gAh + kk + 8);
            cp16(sb2 + ST_A_L * 2 + srow,      gAl + kk);
            cp16(sb2 + ST_A_L * 2 + srow + 16, gAl + kk + 8);
            cp16(sb2 + ST_B_H * 2 + srow,      gWh + kk);
            cp16(sb2 + ST_B_H * 2 + srow + 16, gWh + kk + 8);
            cp16(sb2 + ST_B_L * 2 + srow,      gWl + kk);
            cp16(sb2 + ST_B_L * 2 + srow + 16, gWl + kk + 8);
            cp_commit();
        }
    }

    // ---- epilogue ----
    const int er = lane >> 2;
    const int ec = (lane & 3) * 2;
#pragma unroll
    for (int mt = 0; mt < 4; ++mt) {
#pragma unroll
        for (int nt = 0; nt < 4; ++nt) {
            int col = wn * 32 + nt * 8 + ec;
            float b0 = s_bias[col], b1 = s_bias[col + 1];
#pragma unroll
            for (int h = 0; h < 2; ++h) {
                int row = m0 + wm * 64 + mt * 16 + er + h * 8;
                float v0 = acc[mt][nt][h * 2 + 0] + b0;
                float v1 = acc[mt][nt][h * 2 + 1] + b1;
                if (EPI == 1) { v0 = tanhf(v0); v1 = tanhf(v1); }
                size_t off = (size_t)row * N + n0 + col;
                if (WF32) *(float2*)(Cf + off) = make_float2(v0, v1);
                if (WSPLIT) {
                    __nv_bfloat16 h0, l0, h1, l1;
                    split2(v0, h0, l0);
                    split2(v1, h1, l1);
                    __nv_bfloat162 ph, pl;
                    ph.x = h0; ph.y = h1;
                    pl.x = l0; pl.y = l1;
                    *(__nv_bfloat162*)(Ch + off) = ph;
                    *(__nv_bfloat162*)(Cl + off) = pl;
                }
            }
        }
    }
}

// ---------------- weight transpose+split: W[K,N] f32 -> [N,K] bf16 hi/lo -----------
__global__ void wsplit_kernel(const float* __restrict__ W, __nv_bfloat16* __restrict__ hi,
                              __nv_bfloat16* __restrict__ lo, int K, int N) {
    __shared__ float t[32][33];
    const int n0 = blockIdx.x * 32, k0 = blockIdx.y * 32;
    const int tx = threadIdx.x, ty = threadIdx.y;  // (32, 8)
#pragma unroll
    for (int i = 0; i < 4; i++)
        t[ty + i * 8][tx] = W[(size_t)(k0 + ty + i * 8) * N + n0 + tx];
    __syncthreads();
#pragma unroll
    for (int i = 0; i < 4; i++) {
        int n = ty + i * 8;
        float v = t[tx][n];
        __nv_bfloat16 h, l;
        split2(v, h, l);
        size_t o = (size_t)(n0 + n) * K + k0 + tx;
        hi[o] = h;
        lo[o] = l;
    }
}

// ---------------- reductions / misc -------------------------------------------------
__device__ __forceinline__ float blockReduceSum(float v) {
    __shared__ float sh[32];
    int lane = threadIdx.x & 31, wid = threadIdx.x >> 5;
#pragma unroll
    for (int o = 16; o > 0; o >>= 1) v += __shfl_down_sync(0xffffffffu, v, o);
    if (lane == 0) sh[wid] = v;
    __syncthreads();
    int nw = blockDim.x >> 5;
    v = (threadIdx.x < nw) ? sh[threadIdx.x] : 0.f;
    if (wid == 0) {
#pragma unroll
        for (int o = 16; o > 0; o >>= 1) v += __shfl_down_sync(0xffffffffu, v, o);
    }
    __syncthreads();
    return v;
}

// ---------------- FFMA SGEMM (encoder + distance path, fp32-exact) -----------------
#define BM 128
#define BN 128
#define BK 8

template <int EPI>  // 0: +bias, 1: tanh(+bias), 2: rown[m]+bias[n]-2*acc
__global__ void __launch_bounds__(256)
sgemm_kernel(const float* __restrict__ A, const float* __restrict__ B,
             const float* __restrict__ bias, const float* __restrict__ rown,
             float* __restrict__ C, int M, int N, int K) {
    __shared__ __align__(16) float As[2][BK][BM];
    __shared__ __align__(16) float Bs[2][BK][BN];
    const int tid = threadIdx.x;
    const int tx = tid & 15, ty = tid >> 4;
    const int m0 = blockIdx.y * BM, n0 = blockIdx.x * BN;
    const int arow = tid >> 1, akq = (tid & 1) * 4;
    const float* Aptr = A + (size_t)(m0 + arow) * K + akq;
    const int brow = tid >> 5, bcol = (tid & 31) * 4;
    const float* Bptr = B + (size_t)brow * N + n0 + bcol;
    float acc[8][8];
#pragma unroll
    for (int i = 0; i < 8; i++)
#pragma unroll
        for (int j = 0; j < 8; j++) acc[i][j] = 0.f;
    const int nt = K / BK;
    float4 a4 = *(const float4*)(Aptr);
    float4 b4 = *(const float4*)(Bptr);
    As[0][akq + 0][arow] = a4.x; As[0][akq + 1][arow] = a4.y;
    As[0][akq + 2][arow] = a4.z; As[0][akq + 3][arow] = a4.w;
    *(float4*)&Bs[0][brow][bcol] = b4;
    __syncthreads();
    int cur = 0;
    for (int t = 0; t < nt; t++) {
        if (t + 1 < nt) {
            a4 = *(const float4*)(Aptr + (t + 1) * BK);
            b4 = *(const float4*)(Bptr + (size_t)(t + 1) * BK * N);
        }
#pragma unroll
        for (int kk = 0; kk < BK; kk++) {
            float4 a0 = *(const float4*)&As[cur][kk][ty * 4];
            float4 a1 = *(const float4*)&As[cur][kk][64 + ty * 4];
            float4 b0 = *(const float4*)&Bs[cur][kk][tx * 4];
            float4 b1 = *(const float4*)&Bs[cur][kk][64 + tx * 4];
            float ar[8] = {a0.x, a0.y, a0.z, a0.w, a1.x, a1.y, a1.z, a1.w};
            float br[8] = {b0.x, b0.y, b0.z, b0.w, b1.x, b1.y, b1.z, b1.w};
#pragma unroll
            for (int i = 0; i < 8; i++)
#pragma unroll
                for (int j = 0; j < 8; j++) acc[i][j] = fmaf(ar[i], br[j], acc[i][j]);
        }
        if (t + 1 < nt) {
            int nx = cur ^ 1;
            As[nx][akq + 0][arow] = a4.x; As[nx][akq + 1][arow] = a4.y;
            As[nx][akq + 2][arow] = a4.z; As[nx][akq + 3][arow] = a4.w;
            *(float4*)&Bs[nx][brow][bcol] = b4;
        }
        __syncthreads();
        cur ^= 1;
    }
#pragma unroll
    for (int i = 0; i < 8; i++) {
        int r = m0 + ((i < 4) ? (ty * 4 + i) : (64 + ty * 4 + (i - 4)));
        float rn = (EPI == 2) ? rown[r] : 0.f;
#pragma unroll
        for (int jh = 0; jh < 2; jh++) {
            int c = n0 + jh * 64 + tx * 4;
            float4 bv = *(const float4*)(bias + c);
            const float* ap = &acc[i][jh * 4];
            float4 v;
            if (EPI == 2) {
                v.x = rn + bv.x - 2.f * ap[0];
                v.y = rn + bv.y - 2.f * ap[1];
                v.z = rn + bv.z - 2.f * ap[2];
                v.w = rn + bv.w - 2.f * ap[3];
            } else {
                v.x = ap[0] + bv.x; v.y = ap[1] + bv.y;
                v.z = ap[2] + bv.z; v.w = ap[3] + bv.w;
                if (EPI == 1) {
                    v.x = tanhf(v.x); v.y = tanhf(v.y);
                    v.z = tanhf(v.z); v.w = tanhf(v.w);
                }
            }
            *(float4*)(C + (size_t)r * N + c) = v;
        }
    }
}

// ---------------- small kernels -----------------------------------------------------
__global__ void prep_codebook_kernel(const float* __restrict__ cb) {
    int k = blockIdx.x;
    float s = 0.f;
    for (int d = threadIdx.x; d < OBS; d += blockDim.x) {
        float v = cb[(size_t)k * OBS + d];
        g_cbT[(size_t)d * KCB + k] = v;
        s += v * v;
    }
    s = blockReduceSum(s);
    if (threadIdx.x == 0) g_cnorm[k] = s;
}

__global__ void rownorm_kernel(const float* __restrict__ x, float* __restrict__ out, int D) {
    int b = blockIdx.x;
    const float* r = x + (size_t)b * D;
    float s = 0.f;
    for (int d = threadIdx.x; d < D; d += blockDim.x) {
        float v = r[d];
        s += v * v;
    }
    s = blockReduceSum(s);
    if (threadIdx.x == 0) out[b] = s;
}

__global__ void argmin_kernel(const float* __restrict__ dist, float* __restrict__ prop_out_f) {
    __shared__ float sv[256];
    __shared__ int si[256];
    int b = blockIdx.x;
    const float* r = dist + (size_t)b * KCB;
    float best = INFINITY;
    int bi = KCB;
    for (int k = threadIdx.x; k < KCB; k += 256) {
        float v = r[k];
        if (v < best) { best = v; bi = k; }
    }
    sv[threadIdx.x] = best;
    si[threadIdx.x] = bi;
    __syncthreads();
    for (int s = 128; s > 0; s >>= 1) {
        if (threadIdx.x < s) {
            float ov = sv[threadIdx.x + s];
            int oi = si[threadIdx.x + s];
            if (ov < sv[threadIdx.x] || (ov == sv[threadIdx.x] && oi < si[threadIdx.x])) {
                sv[threadIdx.x] = ov;
                si[threadIdx.x] = oi;
            }
        }
        __syncthreads();
    }
    if (threadIdx.x == 0) {
        g_prop[b] = si[0];
        prop_out_f[b] = (float)si[0];
    }
}

__global__ void gather_kernel(const float* __restrict__ cb, __nv_bfloat16* __restrict__ qh,
                              __nv_bfloat16* __restrict__ ql) {
    size_t i = (size_t)blockIdx.x * blockDim.x + threadIdx.x;  // B*OBS
    int b = (int)(i >> 10);
    int d = (int)(i & 1023);
    float v = cb[(size_t)g_prop[b] * OBS + d];
    g_quant[i] = v;
    __nv_bfloat16 h, l;
    split2(v, h, l);
    qh[i] = h;
    ql[i] = l;
}

__global__ void concat_split_kernel(const float* __restrict__ X, __nv_bfloat16* __restrict__ ch,
                                    __nv_bfloat16* __restrict__ cl) {
    size_t i = (size_t)blockIdx.x * blockDim.x + threadIdx.x;  // B*1536
    int b = (int)(i / 1536);
    int j = (int)(i % 1536);
    float v = (j < OBS) ? X[(size_t)b * OBS + j] : g_dist[(size_t)b * KCB + (j - OBS)];
    __nv_bfloat16 h, l;
    split2(v, h, l);
    ch[i] = h;
    cl[i] = l;
}

__global__ void loss_partial_kernel(const float* __restrict__ dx) {
    const size_t NTOT = (size_t)BSZ * OBS;
    float s1 = 0.f, s2 = 0.f;
    for (size_t i = (size_t)blockIdx.x * blockDim.x + threadIdx.x; i < NTOT;
         i += (size_t)gridDim.x * blockDim.x) {
        float a = dx[i] - g_recon[i];
        s1 += a * a;
        float c = g_enc[i] - g_quant[i];
        s2 += c * c;
    }
    s1 = blockReduceSum(s1);
    __syncthreads();
    s2 = blockReduceSum(s2);
    if (threadIdx.x == 0) {
        g_part[2 * blockIdx.x + 0] = s1;
        g_part[2 * blockIdx.x + 1] = s2;
    }
}

__global__ void finalize_total_kernel(int nb, float* __restrict__ out_total) {
    float s1 = 0.f, s2 = 0.f;
    for (int i = threadIdx.x; i < nb; i += 256) {
        s1 += g_part[2 * i + 0];
        s2 += g_part[2 * i + 1];
    }
    s1 = blockReduceSum(s1);
    __syncthreads();
    s2 = blockReduceSum(s2);
    if (threadIdx.x == 0) {
        const float inv = 1.f / ((float)BSZ * (float)OBS);
        float tot = s1 * inv + 2.f * (s2 * inv);
        g_total[0] = tot;
        out_total[0] = tot;
    }
}

__global__ void policy_kernel(const float* __restrict__ A_, const float* __restrict__ log_std,
                              float* __restrict__ out_loss, float* __restrict__ out_losspi) {
    int b = blockIdx.x;
    int j = threadIdx.x;
    float ls = log_std[j];
    float sd = expf(ls);
    float z = (A_[(size_t)b * OUTD + j] - g_mu[(size_t)b * OUTD + j]) / sd;
    float logp = -0.5f * z * z - ls - 0.5f * LOG2PI_F;
    float term = 1.f / (expf(logp) + 0.1f);
    float lp = blockReduceSum(term);
    if (threadIdx.x == 0) {
        out_losspi[b] = lp;
        out_loss[b] = lp * g_total[0];
    }
}

// ---------------- launch -------------------------------------------------------------
static inline dim3 ggrid(int M, int N) { return dim3(N / 128, M / 128); }

extern "C" void kernel_launch(void* const* d_in, const int* in_sizes, int n_in,
                              void* d_out, int out_size) {
    const float* X        = (const float*)d_in[0];
    const float* Delta_X  = (const float*)d_in[1];
    const float* A        = (const float*)d_in[2];
    const float* enc_w1   = (const float*)d_in[3];
    const float* enc_b1   = (const float*)d_in[4];
    const float* enc_w2   = (const float*)d_in[5];
    const float* enc_b2   = (const float*)d_in[6];
    const float* prenet_w = (const float*)d_in[7];
    const float* prenet_b = (const float*)d_in[8];
    const float* codebook = (const float*)d_in[9];
    const float* postnet_w= (const float*)d_in[10];
    const float* postnet_b= (const float*)d_in[11];
    const float* dec_w1   = (const float*)d_in[12];
    const float* dec_b1   = (const float*)d_in[13];
    const float* dec_w2   = (const float*)d_in[14];
    const float* dec_b2   = (const float*)d_in[15];
    const float* dec_w3   = (const float*)d_in[16];
    const float* dec_b3   = (const float*)d_in[17];
    const float* act_w1   = (const float*)d_in[18];
    const float* act_b1   = (const float*)d_in[19];
    const float* act_w2   = (const float*)d_in[20];
    const float* act_b2   = (const float*)d_in[21];
    const float* act_w3   = (const float*)d_in[22];
    const float* act_b3   = (const float*)d_in[23];
    const float* log_std  = (const float*)d_in[24];

    float* out = (float*)d_out;
    float* out_loss   = out;
    float* out_losspi = out + BSZ;
    float* out_X      = out + 2 * (size_t)BSZ;
    float* out_prop   = out + 2 * (size_t)BSZ + (size_t)BSZ * OBS;
    float* out_total  = out_prop + BSZ;

    float *p_h1, *p_h2, *p_enc, *p_dist, *p_quant, *p_recon, *p_mu, *p_cbT, *p_cnorm, *p_xnorm;
    __nv_bfloat16 *p_wh, *p_wl, *p_ah, *p_al;
    cudaGetSymbolAddress((void**)&p_h1, g_h1);
    cudaGetSymbolAddress((void**)&p_h2, g_h2);
    cudaGetSymbolAddress((void**)&p_enc, g_enc);
    cudaGetSymbolAddress((void**)&p_dist, g_dist);
    cudaGetSymbolAddress((void**)&p_quant, g_quant);
    cudaGetSymbolAddress((void**)&p_recon, g_recon);
    cudaGetSymbolAddress((void**)&p_mu, g_mu);
    cudaGetSymbolAddress((void**)&p_cbT, g_cbT);
    cudaGetSymbolAddress((void**)&p_cnorm, g_cnorm);
    cudaGetSymbolAddress((void**)&p_xnorm, g_xnorm);
    cudaGetSymbolAddress((void**)&p_wh, g_wt_hi);
    cudaGetSymbolAddress((void**)&p_wl, g_wt_lo);
    cudaGetSymbolAddress((void**)&p_ah, g_act_hi);
    cudaGetSymbolAddress((void**)&p_al, g_act_lo);

    cudaFuncSetAttribute(mma_gemm<1, 0, 1>, cudaFuncAttributeMaxDynamicSharedMemorySize, GEMM_SMEM);
    cudaFuncSetAttribute(mma_gemm<0, 1, 0>, cudaFuncAttributeMaxDynamicSharedMemorySize, GEMM_SMEM);

    dim3 tb(32, 8);
    // tensor-core weight transpose + split
    wsplit_kernel<<<dim3(1024 / 32, 1024 / 32), tb>>>(postnet_w, p_wh + O_POST, p_wl + O_POST, 1024, 1024);
    wsplit_kernel<<<dim3(2048 / 32, 1024 / 32), tb>>>(dec_w1, p_wh + O_DEC1, p_wl + O_DEC1, 1024, 2048);
    wsplit_kernel<<<dim3(2048 / 32, 2048 / 32), tb>>>(dec_w2, p_wh + O_DEC2, p_wl + O_DEC2, 2048, 2048);
    wsplit_kernel<<<dim3(1024 / 32, 2048 / 32), tb>>>(dec_w3, p_wh + O_DEC3, p_wl + O_DEC3, 2048, 1024);
    wsplit_kernel<<<dim3(2048 / 32, 1536 / 32), tb>>>(act_w1, p_wh + O_ACT1, p_wl + O_ACT1, 1536, 2048);
    wsplit_kernel<<<dim3(2048 / 32, 2048 / 32), tb>>>(act_w2, p_wh + O_ACT2, p_wl + O_ACT2, 2048, 2048);
    wsplit_kernel<<<dim3(256 / 32, 2048 / 32), tb>>>(act_w3, p_wh + O_ACT3, p_wl + O_ACT3, 2048, 256);
    prep_codebook_kernel<<<KCB, 256>>>(codebook);

    // encoder (fp32 FFMA, keeps argmin exact)
    sgemm_kernel<1><<<dim3(512 / BN, BSZ / BM), 256>>>(Delta_X, enc_w1, enc_b1, nullptr, p_h1, BSZ, 512, 1024);
    sgemm_kernel<1><<<dim3(1024 / BN, BSZ / BM), 256>>>(p_h1, enc_w2, enc_b2, nullptr, p_h2, BSZ, 1024, 512);
    sgemm_kernel<0><<<dim3(1024 / BN, BSZ / BM), 256>>>(p_h2, prenet_w, prenet_b, nullptr, p_enc, BSZ, 1024, 1024);

    // distances + argmin + gather
    rownorm_kernel<<<BSZ, 256>>>(p_enc, p_xnorm, OBS);
    sgemm_kernel<2><<<dim3(KCB / BN, BSZ / BM), 256>>>(p_enc, p_cbT, p_cnorm, p_xnorm, p_dist, BSZ, KCB, OBS);
    argmin_kernel<<<BSZ, 256>>>(p_dist, out_prop);
    gather_kernel<<<(BSZ * OBS) / 256, 256>>>(codebook, p_ah + AO_QNT, p_al + AO_QNT);

    // postnet + decoder (tensor cores, bf16 3-term split)
    mma_gemm<1, 0, 1><<<ggrid(BSZ, 1024), 256, GEMM_SMEM>>>(
        p_ah + AO_QNT, p_al + AO_QNT, p_wh + O_POST, p_wl + O_POST, postnet_b,
        nullptr, p_ah + AO_D0, p_al + AO_D0, BSZ, 1024, 1024);
    mma_gemm<1, 0, 1><<<ggrid(BSZ, 2048), 256, GEMM_SMEM>>>(
        p_ah + AO_D0, p_al + AO_D0, p_wh + O_DEC1, p_wl + O_DEC1, dec_b1,
        nullptr, p_ah + AO_D1, p_al + AO_D1, BSZ, 2048, 1024);
    mma_gemm<1, 0, 1><<<ggrid(BSZ, 2048), 256, GEMM_SMEM>>>(
        p_ah + AO_D1, p_al + AO_D1, p_wh + O_DEC2, p_wl + O_DEC2, dec_b2,
        nullptr, p_ah + AO_D2, p_al + AO_D2, BSZ, 2048, 2048);
    mma_gemm<0, 1, 0><<<ggrid(BSZ, 1024), 256, GEMM_SMEM>>>(
        p_ah + AO_D2, p_al + AO_D2, p_wh + O_DEC3, p_wl + O_DEC3, dec_b3,
        p_recon, nullptr, nullptr, BSZ, 1024, 2048);

    // actor (tensor cores)
    concat_split_kernel<<<((size_t)BSZ * 1536) / 256, 256>>>(X, p_ah + AO_CS, p_al + AO_CS);
    mma_gemm<1, 0, 1><<<ggrid(BSZ, 2048), 256, GEMM_SMEM>>>(
        p_ah + AO_CS, p_al + AO_CS, p_wh + O_ACT1, p_wl + O_ACT1, act_b1,
        nullptr, p_ah + AO_A1, p_al + AO_A1, BSZ, 2048, 1536);
    mma_gemm<1, 0, 1><<<ggrid(BSZ, 2048), 256, GEMM_SMEM>>>(
        p_ah + AO_A1, p_al + AO_A1, p_wh + O_ACT2, p_wl + O_ACT2, act_b2,
        nullptr, p_ah + AO_A2, p_al + AO_A2, BSZ, 2048, 2048);
    mma_gemm<0, 1, 0><<<ggrid(BSZ, 256), 256, GEMM_SMEM>>>(
        p_ah + AO_A2, p_al + AO_A2, p_wh + O_ACT3, p_wl + O_ACT3, act_b3,
        p_mu, nullptr, nullptr, BSZ, 256, 2048);

    // losses
    loss_partial_kernel<<<2048, 256>>>(Delta_X);
    finalize_total_kernel<<<1, 256>>>(2048, out_total);
    policy_kernel<<<BSZ, 256>>>(A, log_std, out_loss, out_losspi);

    // X pass-through
    cudaMemcpyAsync(out_X, X, (size_t)BSZ * OBS * sizeof(float), cudaMemcpyDeviceToDevice);
}

// round 6
// speedup vs baseline: 2.2713x; 1.6529x over previous
#include <cuda_runtime.h>
#include <cuda_bf16.h>
#include <math.h>
#include <stdint.h>

#define BSZ   32768
#define OBS   1024
#define OUTD  256
#define KCB   512
#define LOG2PI_F 1.83787706640934534f

// ---------------- fp32 scratch ---------------------------------------------------
__device__ float g_cbT[OBS * KCB];
__device__ float g_cnorm[KCB];
__device__ float g_xnorm[BSZ];
__device__ float g_h1[(size_t)BSZ * 512];
__device__ float g_h2[(size_t)BSZ * 1024];
__device__ float g_enc[(size_t)BSZ * 1024];
__device__ float g_dist[(size_t)BSZ * 512];
__device__ int   g_prop[BSZ];
__device__ float g_mu[(size_t)BSZ * 256];
__device__ float g_part[2048 * 2];
__device__ float g_total[1];

// decoder computed on the 512 unique codebook rows only
__device__ float g_cb_d0[(size_t)KCB * 1024];
__device__ float g_cb_d1[(size_t)KCB * 2048];
__device__ float g_cb_d2[(size_t)KCB * 2048];
__device__ float g_cb_recon[(size_t)KCB * 1024];

// ---------------- bf16 split activation arena (actor only) -------------------------
#define AO_CS  0ull
#define AO_A1  ((size_t)BSZ * 1536)
#define AO_A2  (AO_A1 + (size_t)BSZ * 2048)
#define AO_TOT (AO_A2 + (size_t)BSZ * 2048)
__device__ __nv_bfloat16 g_act_hi[AO_TOT];
__device__ __nv_bfloat16 g_act_lo[AO_TOT];

// transposed + split actor weights [N][K] bf16
#define O_ACT1  0u
#define O_ACT2  3145728u
#define O_ACT3  7340032u
#define WT_TOTAL 7864320u
__device__ __nv_bfloat16 g_wt_hi[WT_TOTAL];
__device__ __nv_bfloat16 g_wt_lo[WT_TOTAL];

// ---------------- small helpers ----------------------------------------------------
__device__ __forceinline__ uint32_t smem_u32(const void* p) {
    uint32_t a;
    asm("{ .reg .u64 t; cvta.to.shared.u64 t, %1; cvt.u32.u64 %0, t; }" : "=r"(a) : "l"(p));
    return a;
}
__device__ __forceinline__ void cp16(uint32_t sdst, const void* gsrc) {
    uint64_t g;
    asm("cvta.to.global.u64 %0, %1;" : "=l"(g) : "l"(gsrc));
    asm volatile("cp.async.cg.shared.global [%0], [%1], 16;" :: "r"(sdst), "l"(g) : "memory");
}
__device__ __forceinline__ void cp_commit() {
    asm volatile("cp.async.commit_group;" ::: "memory");
}
template <int N>
__device__ __forceinline__ void cp_wait() {
    asm volatile("cp.async.wait_group %0;" :: "n"(N) : "memory");
}
__device__ __forceinline__ void ldsm4(uint32_t& r0, uint32_t& r1, uint32_t& r2, uint32_t& r3,
                                      uint32_t a) {
    asm volatile("ldmatrix.sync.aligned.m8n8.x4.shared.b16 {%0,%1,%2,%3}, [%4];"
                 : "=r"(r0), "=r"(r1), "=r"(r2), "=r"(r3) : "r"(a));
}
__device__ __forceinline__ void mma16816(float* c, const uint32_t* a, const uint32_t* b) {
    asm volatile("mma.sync.aligned.m16n8k16.row.col.f32.bf16.bf16.f32 "
                 "{%0,%1,%2,%3}, {%4,%5,%6,%7}, {%8,%9}, {%0,%1,%2,%3};"
                 : "+f"(c[0]), "+f"(c[1]), "+f"(c[2]), "+f"(c[3])
                 : "r"(a[0]), "r"(a[1]), "r"(a[2]), "r"(a[3]), "r"(b[0]), "r"(b[1]));
}
__device__ __forceinline__ void split2(float v, __nv_bfloat16& h, __nv_bfloat16& l) {
    h = __float2bfloat16(v);
    l = __float2bfloat16(v - __bfloat162float(h));
}

// ---------------- tensor-core GEMM (actor): C[M,N] = epi(A @ W[N,K]^T) -------------
#define PITCH 40
#define ST_A_H 0
#define ST_A_L 5120
#define ST_B_H 10240
#define ST_B_L 15360
#define ST_STRIDE 20480
#define STAGES 3
#define GEMM_SMEM (STAGES * ST_STRIDE * 2)

template <int EPI, int WF32, int WSPLIT>
__global__ void __launch_bounds__(256, 1)
mma_gemm(const __nv_bfloat16* __restrict__ Ah, const __nv_bfloat16* __restrict__ Al,
         const __nv_bfloat16* __restrict__ Wh, const __nv_bfloat16* __restrict__ Wl,
         const float* __restrict__ bias, float* __restrict__ Cf,
         __nv_bfloat16* __restrict__ Ch, __nv_bfloat16* __restrict__ Cl,
         int M, int N, int K) {
    extern __shared__ __nv_bfloat16 sm[];
    __shared__ float s_bias[128];
    const int tid = threadIdx.x;
    const int lane = tid & 31, wid = tid >> 5;
    const int wm = wid >> 2, wn = wid & 3;
    const int m0 = blockIdx.y * 128, n0 = blockIdx.x * 128;
    const uint32_t smb = smem_u32(sm);

    if (tid < 128) s_bias[tid] = bias[n0 + tid];

    const int crow = tid >> 1;
    const int ck = (tid & 1) * 16;
    const __nv_bfloat16* gAh = Ah + (size_t)(m0 + crow) * K + ck;
    const __nv_bfloat16* gAl = Al + (size_t)(m0 + crow) * K + ck;
    const __nv_bfloat16* gWh = Wh + (size_t)(n0 + crow) * K + ck;
    const __nv_bfloat16* gWl = Wl + (size_t)(n0 + crow) * K + ck;
    const uint32_t srow = (uint32_t)(crow * PITCH + ck) * 2;

    const int nk = K >> 5;

#pragma unroll
    for (int s = 0; s < STAGES - 1; ++s) {
        uint32_t sb = smb + (uint32_t)s * (ST_STRIDE * 2);
        int kk = s * 32;
        cp16(sb + ST_A_H * 2 + srow,      gAh + kk);
        cp16(sb + ST_A_H * 2 + srow + 16, gAh + kk + 8);
        cp16(sb + ST_A_L * 2 + srow,      gAl + kk);
        cp16(sb + ST_A_L * 2 + srow + 16, gAl + kk + 8);
        cp16(sb + ST_B_H * 2 + srow,      gWh + kk);
        cp16(sb + ST_B_H * 2 + srow + 16, gWh + kk + 8);
        cp16(sb + ST_B_L * 2 + srow,      gWl + kk);
        cp16(sb + ST_B_L * 2 + srow + 16, gWl + kk + 8);
        cp_commit();
    }

    float acc[4][4][4];
#pragma unroll
    for (int i = 0; i < 4; i++)
#pragma unroll
        for (int j = 0; j < 4; j++)
#pragma unroll
            for (int q = 0; q < 4; q++) acc[i][j][q] = 0.f;

    const int fr = lane & 15;
    const int fc = (lane >> 4) << 3;

    for (int t = 0; t < nk; ++t) {
        cp_wait<STAGES - 2>();
        __syncthreads();
        uint32_t sb = smb + (uint32_t)(t % STAGES) * (ST_STRIDE * 2);
#pragma unroll
        for (int ks = 0; ks < 2; ++ks) {
            uint32_t ah[4][4], al[4][4], bh[4][2], bl[4][2];
#pragma unroll
            for (int mt = 0; mt < 4; ++mt) {
                uint32_t a = sb + ST_A_H * 2 +
                             (uint32_t)((wm * 64 + mt * 16 + fr) * PITCH + ks * 16 + fc) * 2;
                ldsm4(ah[mt][0], ah[mt][1], ah[mt][2], ah[mt][3], a);
                ldsm4(al[mt][0], al[mt][1], al[mt][2], al[mt][3],
                      a + (ST_A_L - ST_A_H) * 2);
            }
#pragma unroll
            for (int pn = 0; pn < 2; ++pn) {
                uint32_t a = sb + ST_B_H * 2 +
                             (uint32_t)((wn * 32 + pn * 16 + fr) * PITCH + ks * 16 + fc) * 2;
                uint32_t r0, r1, r2, r3;
                ldsm4(r0, r1, r2, r3, a);
                bh[pn * 2][0] = r0; bh[pn * 2][1] = r2;
                bh[pn * 2 + 1][0] = r1; bh[pn * 2 + 1][1] = r3;
                ldsm4(r0, r1, r2, r3, a + (ST_B_L - ST_B_H) * 2);
                bl[pn * 2][0] = r0; bl[pn * 2][1] = r2;
                bl[pn * 2 + 1][0] = r1; bl[pn * 2 + 1][1] = r3;
            }
#pragma unroll
            for (int mt = 0; mt < 4; ++mt)
#pragma unroll
                for (int nt = 0; nt < 4; ++nt) {
                    mma16816(acc[mt][nt], ah[mt], bh[nt]);
                    mma16816(acc[mt][nt], ah[mt], bl[nt]);
                    mma16816(acc[mt][nt], al[mt], bh[nt]);
                }
        }
        __syncthreads();
        int tn = t + STAGES - 1;
        if (tn < nk) {
            uint32_t sb2 = smb + (uint32_t)(tn % STAGES) * (ST_STRIDE * 2);
            int kk = tn * 32;
            cp16(sb2 + ST_A_H * 2 + srow,      gAh + kk);
            cp16(sb2 + ST_A_H * 2 + srow + 16, gAh + kk + 8);
            cp16(sb2 + ST_A_L * 2 + srow,      gAl + kk);
            cp16(sb2 + ST_A_L * 2 + srow + 16, gAl + kk + 8);
            cp16(sb2 + ST_B_H * 2 + srow,      gWh + kk);
            cp16(sb2 + ST_B_H * 2 + srow + 16, gWh + kk + 8);
            cp16(sb2 + ST_B_L * 2 + srow,      gWl + kk);
            cp16(sb2 + ST_B_L * 2 + srow + 16, gWl + kk + 8);
            cp_commit();
        }
    }

    const int er = lane >> 2;
    const int ec = (lane & 3) * 2;
#pragma unroll
    for (int mt = 0; mt < 4; ++mt) {
#pragma unroll
        for (int nt = 0; nt < 4; ++nt) {
            int col = wn * 32 + nt * 8 + ec;
            float b0 = s_bias[col], b1 = s_bias[col + 1];
#pragma unroll
            for (int h = 0; h < 2; ++h) {
                int row = m0 + wm * 64 + mt * 16 + er + h * 8;
                float v0 = acc[mt][nt][h * 2 + 0] + b0;
                float v1 = acc[mt][nt][h * 2 + 1] + b1;
                if (EPI == 1) { v0 = tanhf(v0); v1 = tanhf(v1); }
                size_t off = (size_t)row * N + n0 + col;
                if (WF32) *(float2*)(Cf + off) = make_float2(v0, v1);
                if (WSPLIT) {
                    __nv_bfloat16 h0, l0, h1, l1;
                    split2(v0, h0, l0);
                    split2(v1, h1, l1);
                    __nv_bfloat162 ph, pl;
                    ph.x = h0; ph.y = h1;
                    pl.x = l0; pl.y = l1;
                    *(__nv_bfloat162*)(Ch + off) = ph;
                    *(__nv_bfloat162*)(Cl + off) = pl;
                }
            }
        }
    }
}

// ---------------- weight transpose+split: W[K,N] f32 -> [N,K] bf16 hi/lo ------------
__global__ void wsplit_kernel(const float* __restrict__ W, __nv_bfloat16* __restrict__ hi,
                              __nv_bfloat16* __restrict__ lo, int K, int N) {
    __shared__ float t[32][33];
    const int n0 = blockIdx.x * 32, k0 = blockIdx.y * 32;
    const int tx = threadIdx.x, ty = threadIdx.y;
#pragma unroll
    for (int i = 0; i < 4; i++)
        t[ty + i * 8][tx] = W[(size_t)(k0 + ty + i * 8) * N + n0 + tx];
    __syncthreads();
#pragma unroll
    for (int i = 0; i < 4; i++) {
        int n = ty + i * 8;
        float v = t[tx][n];
        __nv_bfloat16 h, l;
        split2(v, h, l);
        size_t o = (size_t)(n0 + n) * K + k0 + tx;
        hi[o] = h;
        lo[o] = l;
    }
}

// ---------------- reductions / misc --------------------------------------------------
__device__ __forceinline__ float blockReduceSum(float v) {
    __shared__ float sh[32];
    int lane = threadIdx.x & 31, wid = threadIdx.x >> 5;
#pragma unroll
    for (int o = 16; o > 0; o >>= 1) v += __shfl_down_sync(0xffffffffu, v, o);
    if (lane == 0) sh[wid] = v;
    __syncthreads();
    int nw = blockDim.x >> 5;
    v = (threadIdx.x < nw) ? sh[threadIdx.x] : 0.f;
    if (wid == 0) {
#pragma unroll
        for (int o = 16; o > 0; o >>= 1) v += __shfl_down_sync(0xffffffffu, v, o);
    }
    __syncthreads();
    return v;
}

// ---------------- FFMA SGEMM (encoder / dist / decoder-512, fp32-exact) --------------
#define BM 128
#define BN 128
#define BK 8

template <int EPI>  // 0: +bias, 1: tanh(+bias), 2: rown[m]+bias[n]-2*acc
__global__ void __launch_bounds__(256)
sgemm_kernel(const float* __restrict__ A, const float* __restrict__ B,
             const float* __restrict__ bias, const float* __restrict__ rown,
             float* __restrict__ C, int M, int N, int K) {
    __shared__ __align__(16) float As[2][BK][BM];
    __shared__ __align__(16) float Bs[2][BK][BN];
    const int tid = threadIdx.x;
    const int tx = tid & 15, ty = tid >> 4;
    const int m0 = blockIdx.y * BM, n0 = blockIdx.x * BN;
    const int arow = tid >> 1, akq = (tid & 1) * 4;
    const float* Aptr = A + (size_t)(m0 + arow) * K + akq;
    const int brow = tid >> 5, bcol = (tid & 31) * 4;
    const float* Bptr = B + (size_t)brow * N + n0 + bcol;
    float acc[8][8];
#pragma unroll
    for (int i = 0; i < 8; i++)
#pragma unroll
        for (int j = 0; j < 8; j++) acc[i][j] = 0.f;
    const int nt = K / BK;
    float4 a4 = *(const float4*)(Aptr);
    float4 b4 = *(const float4*)(Bptr);
    As[0][akq + 0][arow] = a4.x; As[0][akq + 1][arow] = a4.y;
    As[0][akq + 2][arow] = a4.z; As[0][akq + 3][arow] = a4.w;
    *(float4*)&Bs[0][brow][bcol] = b4;
    __syncthreads();
    int cur = 0;
    for (int t = 0; t < nt; t++) {
        if (t + 1 < nt) {
            a4 = *(const float4*)(Aptr + (t + 1) * BK);
            b4 = *(const float4*)(Bptr + (size_t)(t + 1) * BK * N);
        }
#pragma unroll
        for (int kk = 0; kk < BK; kk++) {
            float4 a0 = *(const float4*)&As[cur][kk][ty * 4];
            float4 a1 = *(const float4*)&As[cur][kk][64 + ty * 4];
            float4 b0 = *(const float4*)&Bs[cur][kk][tx * 4];
            float4 b1 = *(const float4*)&Bs[cur][kk][64 + tx * 4];
            float ar[8] = {a0.x, a0.y, a0.z, a0.w, a1.x, a1.y, a1.z, a1.w};
            float br[8] = {b0.x, b0.y, b0.z, b0.w, b1.x, b1.y, b1.z, b1.w};
#pragma unroll
            for (int i = 0; i < 8; i++)
#pragma unroll
                for (int j = 0; j < 8; j++) acc[i][j] = fmaf(ar[i], br[j], acc[i][j]);
        }
        if (t + 1 < nt) {
            int nx = cur ^ 1;
            As[nx][akq + 0][arow] = a4.x; As[nx][akq + 1][arow] = a4.y;
            As[nx][akq + 2][arow] = a4.z; As[nx][akq + 3][arow] = a4.w;
            *(float4*)&Bs[nx][brow][bcol] = b4;
        }
        __syncthreads();
        cur ^= 1;
    }
#pragma unroll
    for (int i = 0; i < 8; i++) {
        int r = m0 + ((i < 4) ? (ty * 4 + i) : (64 + ty * 4 + (i - 4)));
        float rn = (EPI == 2) ? rown[r] : 0.f;
#pragma unroll
        for (int jh = 0; jh < 2; jh++) {
            int c = n0 + jh * 64 + tx * 4;
            float4 bv = *(const float4*)(bias + c);
            const float* ap = &acc[i][jh * 4];
            float4 v;
            if (EPI == 2) {
                v.x = rn + bv.x - 2.f * ap[0];
                v.y = rn + bv.y - 2.f * ap[1];
                v.z = rn + bv.z - 2.f * ap[2];
                v.w = rn + bv.w - 2.f * ap[3];
            } else {
                v.x = ap[0] + bv.x; v.y = ap[1] + bv.y;
                v.z = ap[2] + bv.z; v.w = ap[3] + bv.w;
                if (EPI == 1) {
                    v.x = tanhf(v.x); v.y = tanhf(v.y);
                    v.z = tanhf(v.z); v.w = tanhf(v.w);
                }
            }
            *(float4*)(C + (size_t)r * N + c) = v;
        }
    }
}

// ---------------- small kernels --------------------------------------------------------
__global__ void prep_codebook_kernel(const float* __restrict__ cb) {
    int k = blockIdx.x;
    float s = 0.f;
    for (int d = threadIdx.x; d < OBS; d += blockDim.x) {
        float v = cb[(size_t)k * OBS + d];
        g_cbT[(size_t)d * KCB + k] = v;
        s += v * v;
    }
    s = blockReduceSum(s);
    if (threadIdx.x == 0) g_cnorm[k] = s;
}

__global__ void rownorm_kernel(const float* __restrict__ x, float* __restrict__ out, int D) {
    int b = blockIdx.x;
    const float* r = x + (size_t)b * D;
    float s = 0.f;
    for (int d = threadIdx.x; d < D; d += blockDim.x) {
        float v = r[d];
        s += v * v;
    }
    s = blockReduceSum(s);
    if (threadIdx.x == 0) out[b] = s;
}

__global__ void argmin_kernel(const float* __restrict__ dist, float* __restrict__ prop_out_f) {
    __shared__ float sv[256];
    __shared__ int si[256];
    int b = blockIdx.x;
    const float* r = dist + (size_t)b * KCB;
    float best = INFINITY;
    int bi = KCB;
    for (int k = threadIdx.x; k < KCB; k += 256) {
        float v = r[k];
        if (v < best) { best = v; bi = k; }
    }
    sv[threadIdx.x] = best;
    si[threadIdx.x] = bi;
    __syncthreads();
    for (int s = 128; s > 0; s >>= 1) {
        if (threadIdx.x < s) {
            float ov = sv[threadIdx.x + s];
            int oi = si[threadIdx.x + s];
            if (ov < sv[threadIdx.x] || (ov == sv[threadIdx.x] && oi < si[threadIdx.x])) {
                sv[threadIdx.x] = ov;
                si[threadIdx.x] = oi;
            }
        }
        __syncthreads();
    }
    if (threadIdx.x == 0) {
        g_prop[b] = si[0];
        prop_out_f[b] = (float)si[0];
    }
}

__global__ void concat_split_kernel(const float* __restrict__ X, __nv_bfloat16* __restrict__ ch,
                                    __nv_bfloat16* __restrict__ cl) {
    size_t i = (size_t)blockIdx.x * blockDim.x + threadIdx.x;  // B*1536
    int b = (int)(i / 1536);
    int j = (int)(i % 1536);
    float v = (j < OBS) ? X[(size_t)b * OBS + j] : g_dist[(size_t)b * KCB + (j - OBS)];
    __nv_bfloat16 h, l;
    split2(v, h, l);
    ch[i] = h;
    cl[i] = l;
}

// loss: gathers recon and quantized from the 512-row decoder/codebook tables
__global__ void loss_partial_kernel(const float* __restrict__ dx, const float* __restrict__ cb) {
    const size_t NTOT = (size_t)BSZ * OBS;
    float s1 = 0.f, s2 = 0.f;
    for (size_t i = (size_t)blockIdx.x * blockDim.x + threadIdx.x; i < NTOT;
         i += (size_t)gridDim.x * blockDim.x) {
        int b = (int)(i >> 10);
        int d = (int)(i & 1023);
        size_t ko = (size_t)g_prop[b] * OBS + d;
        float a = dx[i] - g_cb_recon[ko];
        s1 += a * a;
        float c = g_enc[i] - cb[ko];
        s2 += c * c;
    }
    s1 = blockReduceSum(s1);
    __syncthreads();
    s2 = blockReduceSum(s2);
    if (threadIdx.x == 0) {
        g_part[2 * blockIdx.x + 0] = s1;
        g_part[2 * blockIdx.x + 1] = s2;
    }
}

__global__ void finalize_total_kernel(int nb, float* __restrict__ out_total) {
    float s1 = 0.f, s2 = 0.f;
    for (int i = threadIdx.x; i < nb; i += 256) {
        s1 += g_part[2 * i + 0];
        s2 += g_part[2 * i + 1];
    }
    s1 = blockReduceSum(s1);
    __syncthreads();
    s2 = blockReduceSum(s2);
    if (threadIdx.x == 0) {
        const float inv = 1.f / ((float)BSZ * (float)OBS);
        float tot = s1 * inv + 2.f * (s2 * inv);
        g_total[0] = tot;
        out_total[0] = tot;
    }
}

__global__ void policy_kernel(const float* __restrict__ A_, const float* __restrict__ log_std,
                              float* __restrict__ out_loss, float* __restrict__ out_losspi) {
    int b = blockIdx.x;
    int j = threadIdx.x;
    float ls = log_std[j];
    float sd = expf(ls);
    float z = (A_[(size_t)b * OUTD + j] - g_mu[(size_t)b * OUTD + j]) / sd;
    float logp = -0.5f * z * z - ls - 0.5f * LOG2PI_F;
    float term = 1.f / (expf(logp) + 0.1f);
    float lp = blockReduceSum(term);
    if (threadIdx.x == 0) {
        out_losspi[b] = lp;
        out_loss[b] = lp * g_total[0];
    }
}

// ---------------- launch ----------------------------------------------------------------
static inline dim3 ggrid(int M, int N) { return dim3(N / 128, M / 128); }

extern "C" void kernel_launch(void* const* d_in, const int* in_sizes, int n_in,
                              void* d_out, int out_size) {
    const float* X        = (const float*)d_in[0];
    const float* Delta_X  = (const float*)d_in[1];
    const float* A        = (const float*)d_in[2];
    const float* enc_w1   = (const float*)d_in[3];
    const float* enc_b1   = (const float*)d_in[4];
    const float* enc_w2   = (const float*)d_in[5];
    const float* enc_b2   = (const float*)d_in[6];
    const float* prenet_w = (const float*)d_in[7];
    const float* prenet_b = (const float*)d_in[8];
    const float* codebook = (const float*)d_in[9];
    const float* postnet_w= (const float*)d_in[10];
    const float* postnet_b= (const float*)d_in[11];
    const float* dec_w1   = (const float*)d_in[12];
    const float* dec_b1   = (const float*)d_in[13];
    const float* dec_w2   = (const float*)d_in[14];
    const float* dec_b2   = (const float*)d_in[15];
    const float* dec_w3   = (const float*)d_in[16];
    const float* dec_b3   = (const float*)d_in[17];
    const float* act_w1   = (const float*)d_in[18];
    const float* act_b1   = (const float*)d_in[19];
    const float* act_w2   = (const float*)d_in[20];
    const float* act_b2   = (const float*)d_in[21];
    const float* act_w3   = (const float*)d_in[22];
    const float* act_b3   = (const float*)d_in[23];
    const float* log_std  = (const float*)d_in[24];

    float* out = (float*)d_out;
    float* out_loss   = out;
    float* out_losspi = out + BSZ;
    float* out_X      = out + 2 * (size_t)BSZ;
    float* out_prop   = out + 2 * (size_t)BSZ + (size_t)BSZ * OBS;
    float* out_total  = out_prop + BSZ;

    float *p_h1, *p_h2, *p_enc, *p_dist, *p_mu, *p_cbT, *p_cnorm, *p_xnorm;
    float *p_d0, *p_d1, *p_d2, *p_rec;
    __nv_bfloat16 *p_wh, *p_wl, *p_ah, *p_al;
    cudaGetSymbolAddress((void**)&p_h1, g_h1);
    cudaGetSymbolAddress((void**)&p_h2, g_h2);
    cudaGetSymbolAddress((void**)&p_enc, g_enc);
    cudaGetSymbolAddress((void**)&p_dist, g_dist);
    cudaGetSymbolAddress((void**)&p_mu, g_mu);
    cudaGetSymbolAddress((void**)&p_cbT, g_cbT);
    cudaGetSymbolAddress((void**)&p_cnorm, g_cnorm);
    cudaGetSymbolAddress((void**)&p_xnorm, g_xnorm);
    cudaGetSymbolAddress((void**)&p_d0, g_cb_d0);
    cudaGetSymbolAddress((void**)&p_d1, g_cb_d1);
    cudaGetSymbolAddress((void**)&p_d2, g_cb_d2);
    cudaGetSymbolAddress((void**)&p_rec, g_cb_recon);
    cudaGetSymbolAddress((void**)&p_wh, g_wt_hi);
    cudaGetSymbolAddress((void**)&p_wl, g_wt_lo);
    cudaGetSymbolAddress((void**)&p_ah, g_act_hi);
    cudaGetSymbolAddress((void**)&p_al, g_act_lo);

    cudaFuncSetAttribute(mma_gemm<1, 0, 1>, cudaFuncAttributeMaxDynamicSharedMemorySize, GEMM_SMEM);
    cudaFuncSetAttribute(mma_gemm<0, 1, 0>, cudaFuncAttributeMaxDynamicSharedMemorySize, GEMM_SMEM);

    dim3 tb(32, 8);
    // actor weight transpose + split
    wsplit_kernel<<<dim3(2048 / 32, 1536 / 32), tb>>>(act_w1, p_wh + O_ACT1, p_wl + O_ACT1, 1536, 2048);
    wsplit_kernel<<<dim3(2048 / 32, 2048 / 32), tb>>>(act_w2, p_wh + O_ACT2, p_wl + O_ACT2, 2048, 2048);
    wsplit_kernel<<<dim3(256 / 32, 2048 / 32), tb>>>(act_w3, p_wh + O_ACT3, p_wl + O_ACT3, 2048, 256);
    prep_codebook_kernel<<<KCB, 256>>>(codebook);

    // decoder on 512 unique codebook rows (exact fp32, ~10 GF)
    sgemm_kernel<1><<<dim3(1024 / BN, KCB / BM), 256>>>(codebook, postnet_w, postnet_b, nullptr, p_d0, KCB, 1024, 1024);
    sgemm_kernel<1><<<dim3(2048 / BN, KCB / BM), 256>>>(p_d0, dec_w1, dec_b1, nullptr, p_d1, KCB, 2048, 1024);
    sgemm_kernel<1><<<dim3(2048 / BN, KCB / BM), 256>>>(p_d1, dec_w2, dec_b2, nullptr, p_d2, KCB, 2048, 2048);
    sgemm_kernel<0><<<dim3(1024 / BN, KCB / BM), 256>>>(p_d2, dec_w3, dec_b3, nullptr, p_rec, KCB, 1024, 2048);

    // encoder (fp32 FFMA, keeps argmin exact)
    sgemm_kernel<1><<<dim3(512 / BN, BSZ / BM), 256>>>(Delta_X, enc_w1, enc_b1, nullptr, p_h1, BSZ, 512, 1024);
    sgemm_kernel<1><<<dim3(1024 / BN, BSZ / BM), 256>>>(p_h1, enc_w2, enc_b2, nullptr, p_h2, BSZ, 1024, 512);
    sgemm_kernel<0><<<dim3(1024 / BN, BSZ / BM), 256>>>(p_h2, prenet_w, prenet_b, nullptr, p_enc, BSZ, 1024, 1024);

    // distances + argmin
    rownorm_kernel<<<BSZ, 256>>>(p_enc, p_xnorm, OBS);
    sgemm_kernel<2><<<dim3(KCB / BN, BSZ / BM), 256>>>(p_enc, p_cbT, p_cnorm, p_xnorm, p_dist, BSZ, KCB, OBS);
    argmin_kernel<<<BSZ, 256>>>(p_dist, out_prop);

    // actor (tensor cores, bf16 3-term split)
    concat_split_kernel<<<((size_t)BSZ * 1536) / 256, 256>>>(X, p_ah + AO_CS, p_al + AO_CS);
    mma_gemm<1, 0, 1><<<ggrid(BSZ, 2048), 256, GEMM_SMEM>>>(
        p_ah + AO_CS, p_al + AO_CS, p_wh + O_ACT1, p_wl + O_ACT1, act_b1,
        nullptr, p_ah + AO_A1, p_al + AO_A1, BSZ, 2048, 1536);
    mma_gemm<1, 0, 1><<<ggrid(BSZ, 2048), 256, GEMM_SMEM>>>(
        p_ah + AO_A1, p_al + AO_A1, p_wh + O_ACT2, p_wl + O_ACT2, act_b2,
        nullptr, p_ah + AO_A2, p_al + AO_A2, BSZ, 2048, 2048);
    mma_gemm<0, 1, 0><<<ggrid(BSZ, 256), 256, GEMM_SMEM>>>(
        p_ah + AO_A2, p_al + AO_A2, p_wh + O_ACT3, p_wl + O_ACT3, act_b3,
        p_mu, nullptr, nullptr, BSZ, 256, 2048);

    // losses (recon + quantized gathered from 512-row tables)
    loss_partial_kernel<<<2048, 256>>>(Delta_X, codebook);
    finalize_total_kernel<<<1, 256>>>(2048, out_total);
    policy_kernel<<<BSZ, 256>>>(A, log_std, out_loss, out_losspi);

    // X pass-through
    cudaMemcpyAsync(out_X, X, (size_t)BSZ * OBS * sizeof(float), cudaMemcpyDeviceToDevice);
}

// round 7
// speedup vs baseline: 2.3599x; 1.0390x over previous
#include <cuda_runtime.h>
#include <cuda_bf16.h>
#include <math.h>
#include <stdint.h>

#define BSZ   32768
#define OBS   1024
#define OUTD  256
#define KCB   512
#define LOG2PI_F 1.83787706640934534f

// ---------------- fp32 scratch ---------------------------------------------------
__device__ float g_cbT[OBS * KCB];
__device__ float g_cnorm[KCB];
__device__ float g_xnorm[BSZ];
__device__ float g_h1[(size_t)BSZ * 512];
__device__ float g_h2[(size_t)BSZ * 1024];
__device__ float g_enc[(size_t)BSZ * 1024];
__device__ float g_dist[(size_t)BSZ * 512];
__device__ int   g_prop[BSZ];
__device__ float g_mu[(size_t)BSZ * 256];
__device__ float g_part[2048 * 2];
__device__ float g_total[1];
__device__ float g_zb[2048];                       // never written: stays zero
__device__ float g_p1[(size_t)BSZ * 2048];         // act1 X-part partial (fp32)

// decoder computed on the 512 unique codebook rows only
__device__ float g_cb_d0[(size_t)KCB * 1024];
__device__ float g_cb_d1[(size_t)KCB * 2048];
__device__ float g_cb_d2[(size_t)KCB * 2048];
__device__ float g_cb_recon[(size_t)KCB * 1024];

// ---------------- bf16 split activation arenas -------------------------------------
__device__ __nv_bfloat16 g_xs_hi[(size_t)BSZ * 1024];
__device__ __nv_bfloat16 g_xs_lo[(size_t)BSZ * 1024];
__device__ __nv_bfloat16 g_ds_hi[(size_t)BSZ * 512];
__device__ __nv_bfloat16 g_ds_lo[(size_t)BSZ * 512];
__device__ __nv_bfloat16 g_a1_hi[(size_t)BSZ * 2048];
__device__ __nv_bfloat16 g_a1_lo[(size_t)BSZ * 2048];
__device__ __nv_bfloat16 g_a2_hi[(size_t)BSZ * 2048];
__device__ __nv_bfloat16 g_a2_lo[(size_t)BSZ * 2048];

// transposed + split actor weights [N][K] bf16
#define O_A1X   0u
#define O_A1D   2097152u
#define O_ACT2  3145728u
#define O_ACT3  7340032u
#define WT_TOTAL 7864320u
__device__ __nv_bfloat16 g_wt_hi[WT_TOTAL];
__device__ __nv_bfloat16 g_wt_lo[WT_TOTAL];

// ---------------- small helpers ----------------------------------------------------
__device__ __forceinline__ uint32_t smem_u32(const void* p) {
    uint32_t a;
    asm("{ .reg .u64 t; cvta.to.shared.u64 t, %1; cvt.u32.u64 %0, t; }" : "=r"(a) : "l"(p));
    return a;
}
__device__ __forceinline__ void cp16(uint32_t sdst, const void* gsrc) {
    uint64_t g;
    asm("cvta.to.global.u64 %0, %1;" : "=l"(g) : "l"(gsrc));
    asm volatile("cp.async.cg.shared.global [%0], [%1], 16;" :: "r"(sdst), "l"(g) : "memory");
}
__device__ __forceinline__ void cp_commit() {
    asm volatile("cp.async.commit_group;" ::: "memory");
}
template <int N>
__device__ __forceinline__ void cp_wait() {
    asm volatile("cp.async.wait_group %0;" :: "n"(N) : "memory");
}
__device__ __forceinline__ void ldsm4(uint32_t& r0, uint32_t& r1, uint32_t& r2, uint32_t& r3,
                                      uint32_t a) {
    asm volatile("ldmatrix.sync.aligned.m8n8.x4.shared.b16 {%0,%1,%2,%3}, [%4];"
                 : "=r"(r0), "=r"(r1), "=r"(r2), "=r"(r3) : "r"(a));
}
__device__ __forceinline__ void mma16816(float* c, const uint32_t* a, const uint32_t* b) {
    asm volatile("mma.sync.aligned.m16n8k16.row.col.f32.bf16.bf16.f32 "
                 "{%0,%1,%2,%3}, {%4,%5,%6,%7}, {%8,%9}, {%0,%1,%2,%3};"
                 : "+f"(c[0]), "+f"(c[1]), "+f"(c[2]), "+f"(c[3])
                 : "r"(a[0]), "r"(a[1]), "r"(a[2]), "r"(a[3]), "r"(b[0]), "r"(b[1]));
}
__device__ __forceinline__ void split2(float v, __nv_bfloat16& h, __nv_bfloat16& l) {
    h = __float2bfloat16(v);
    l = __float2bfloat16(v - __bfloat162float(h));
}

// ---------------- tensor-core GEMM: C[M,N] = epi(A @ W[N,K]^T [+ Cin]) --------------
#define PITCH 40
#define ST_A_H 0
#define ST_A_L 5120
#define ST_B_H 10240
#define ST_B_L 15360
#define ST_STRIDE 20480
#define STAGES 3
#define GEMM_SMEM (STAGES * ST_STRIDE * 2)

template <int EPI, int WF32, int WSPLIT, int ADDIN>
__global__ void __launch_bounds__(256, 1)
mma_gemm(const __nv_bfloat16* __restrict__ Ah, const __nv_bfloat16* __restrict__ Al,
         const __nv_bfloat16* __restrict__ Wh, const __nv_bfloat16* __restrict__ Wl,
         const float* __restrict__ bias, const float* __restrict__ Cin,
         float* __restrict__ Cf,
         __nv_bfloat16* __restrict__ Ch, __nv_bfloat16* __restrict__ Cl,
         int M, int N, int K) {
    extern __shared__ __nv_bfloat16 sm[];
    __shared__ float s_bias[128];
    const int tid = threadIdx.x;
    const int lane = tid & 31, wid = tid >> 5;
    const int wm = wid >> 2, wn = wid & 3;
    const int m0 = blockIdx.y * 128, n0 = blockIdx.x * 128;
    const uint32_t smb = smem_u32(sm);

    if (tid < 128) s_bias[tid] = bias[n0 + tid];

    const int crow = tid >> 1;
    const int ck = (tid & 1) * 16;
    const __nv_bfloat16* gAh = Ah + (size_t)(m0 + crow) * K + ck;
    const __nv_bfloat16* gAl = Al + (size_t)(m0 + crow) * K + ck;
    const __nv_bfloat16* gWh = Wh + (size_t)(n0 + crow) * K + ck;
    const __nv_bfloat16* gWl = Wl + (size_t)(n0 + crow) * K + ck;
    const uint32_t srow = (uint32_t)(crow * PITCH + ck) * 2;

    const int nk = K >> 5;

#pragma unroll
    for (int s = 0; s < STAGES - 1; ++s) {
        uint32_t sb = smb + (uint32_t)s * (ST_STRIDE * 2);
        int kk = s * 32;
        cp16(sb + ST_A_H * 2 + srow,      gAh + kk);
        cp16(sb + ST_A_H * 2 + srow + 16, gAh + kk + 8);
        cp16(sb + ST_A_L * 2 + srow,      gAl + kk);
        cp16(sb + ST_A_L * 2 + srow + 16, gAl + kk + 8);
        cp16(sb + ST_B_H * 2 + srow,      gWh + kk);
        cp16(sb + ST_B_H * 2 + srow + 16, gWh + kk + 8);
        cp16(sb + ST_B_L * 2 + srow,      gWl + kk);
        cp16(sb + ST_B_L * 2 + srow + 16, gWl + kk + 8);
        cp_commit();
    }

    float acc[4][4][4];
#pragma unroll
    for (int i = 0; i < 4; i++)
#pragma unroll
        for (int j = 0; j < 4; j++)
#pragma unroll
            for (int q = 0; q < 4; q++) acc[i][j][q] = 0.f;

    const int fr = lane & 15;
    const int fc = (lane >> 4) << 3;

    for (int t = 0; t < nk; ++t) {
        cp_wait<STAGES - 2>();
        __syncthreads();
        uint32_t sb = smb + (uint32_t)(t % STAGES) * (ST_STRIDE * 2);
#pragma unroll
        for (int ks = 0; ks < 2; ++ks) {
            uint32_t ah[4][4], al[4][4], bh[4][2], bl[4][2];
#pragma unroll
            for (int mt = 0; mt < 4; ++mt) {
                uint32_t a = sb + ST_A_H * 2 +
                             (uint32_t)((wm * 64 + mt * 16 + fr) * PITCH + ks * 16 + fc) * 2;
                ldsm4(ah[mt][0], ah[mt][1], ah[mt][2], ah[mt][3], a);
                ldsm4(al[mt][0], al[mt][1], al[mt][2], al[mt][3],
                      a + (ST_A_L - ST_A_H) * 2);
            }
#pragma unroll
            for (int pn = 0; pn < 2; ++pn) {
                uint32_t a = sb + ST_B_H * 2 +
                             (uint32_t)((wn * 32 + pn * 16 + fr) * PITCH + ks * 16 + fc) * 2;
                uint32_t r0, r1, r2, r3;
                ldsm4(r0, r1, r2, r3, a);
                bh[pn * 2][0] = r0; bh[pn * 2][1] = r2;
                bh[pn * 2 + 1][0] = r1; bh[pn * 2 + 1][1] = r3;
                ldsm4(r0, r1, r2, r3, a + (ST_B_L - ST_B_H) * 2);
                bl[pn * 2][0] = r0; bl[pn * 2][1] = r2;
                bl[pn * 2 + 1][0] = r1; bl[pn * 2 + 1][1] = r3;
            }
#pragma unroll
            for (int mt = 0; mt < 4; ++mt)
#pragma unroll
                for (int nt = 0; nt < 4; ++nt) {
                    mma16816(acc[mt][nt], ah[mt], bh[nt]);
                    mma16816(acc[mt][nt], ah[mt], bl[nt]);
                    mma16816(acc[mt][nt], al[mt], bh[nt]);
                }
        }
        __syncthreads();
        int tn = t + STAGES - 1;
        if (tn < nk) {
            uint32_t sb2 = smb + (uint32_t)(tn % STAGES) * (ST_STRIDE * 2);
            int kk = tn * 32;
            cp16(sb2 + ST_A_H * 2 + srow,      gAh + kk);
            cp16(sb2 + ST_A_H * 2 + srow + 16, gAh + kk + 8);
            cp16(sb2 + ST_A_L * 2 + srow,      gAl + kk);
            cp16(sb2 + ST_A_L * 2 + srow + 16, gAl + kk + 8);
            cp16(sb2 + ST_B_H * 2 + srow,      gWh + kk);
            cp16(sb2 + ST_B_H * 2 + srow + 16, gWh + kk + 8);
            cp16(sb2 + ST_B_L * 2 + srow,      gWl + kk);
            cp16(sb2 + ST_B_L * 2 + srow + 16, gWl + kk + 8);
            cp_commit();
        }
    }

    const int er = lane >> 2;
    const int ec = (lane & 3) * 2;
#pragma unroll
    for (int mt = 0; mt < 4; ++mt) {
#pragma unroll
        for (int nt = 0; nt < 4; ++nt) {
            int col = wn * 32 + nt * 8 + ec;
            float b0 = s_bias[col], b1 = s_bias[col + 1];
#pragma unroll
            for (int h = 0; h < 2; ++h) {
                int row = m0 + wm * 64 + mt * 16 + er + h * 8;
                size_t off = (size_t)row * N + n0 + col;
                float v0 = acc[mt][nt][h * 2 + 0] + b0;
                float v1 = acc[mt][nt][h * 2 + 1] + b1;
                if (ADDIN) {
                    float2 ci = *(const float2*)(Cin + off);
                    v0 += ci.x;
                    v1 += ci.y;
                }
                if (EPI == 1) { v0 = tanhf(v0); v1 = tanhf(v1); }
                if (WF32) *(float2*)(Cf + off) = make_float2(v0, v1);
                if (WSPLIT) {
                    __nv_bfloat16 h0, l0, h1, l1;
                    split2(v0, h0, l0);
                    split2(v1, h1, l1);
                    __nv_bfloat162 ph, pl;
                    ph.x = h0; ph.y = h1;
                    pl.x = l0; pl.y = l1;
                    *(__nv_bfloat162*)(Ch + off) = ph;
                    *(__nv_bfloat162*)(Cl + off) = pl;
                }
            }
        }
    }
}

// ---------------- weight transpose+split: W[K,N] f32 -> [N,K] bf16 hi/lo ------------
__global__ void wsplit_kernel(const float* __restrict__ W, __nv_bfloat16* __restrict__ hi,
                              __nv_bfloat16* __restrict__ lo, int K, int N) {
    __shared__ float t[32][33];
    const int n0 = blockIdx.x * 32, k0 = blockIdx.y * 32;
    const int tx = threadIdx.x, ty = threadIdx.y;
#pragma unroll
    for (int i = 0; i < 4; i++)
        t[ty + i * 8][tx] = W[(size_t)(k0 + ty + i * 8) * N + n0 + tx];
    __syncthreads();
#pragma unroll
    for (int i = 0; i < 4; i++) {
        int n = ty + i * 8;
        float v = t[tx][n];
        __nv_bfloat16 h, l;
        split2(v, h, l);
        size_t o = (size_t)(n0 + n) * K + k0 + tx;
        hi[o] = h;
        lo[o] = l;
    }
}

// ---------------- reductions / misc --------------------------------------------------
__device__ __forceinline__ float blockReduceSum(float v) {
    __shared__ float sh[32];
    int lane = threadIdx.x & 31, wid = threadIdx.x >> 5;
#pragma unroll
    for (int o = 16; o > 0; o >>= 1) v += __shfl_down_sync(0xffffffffu, v, o);
    if (lane == 0) sh[wid] = v;
    __syncthreads();
    int nw = blockDim.x >> 5;
    v = (threadIdx.x < nw) ? sh[threadIdx.x] : 0.f;
    if (wid == 0) {
#pragma unroll
        for (int o = 16; o > 0; o >>= 1) v += __shfl_down_sync(0xffffffffu, v, o);
    }
    __syncthreads();
    return v;
}

// ---------------- FFMA SGEMM (encoder / dist / decoder-512, fp32-exact) --------------
#define BM 128
#define BN 128
#define BK 8

template <int EPI>  // 0: +bias, 1: tanh(+bias), 2: rown[m]+bias[n]-2*acc (+bf16 split out)
__global__ void __launch_bounds__(256)
sgemm_kernel(const float* __restrict__ A, const float* __restrict__ B,
             const float* __restrict__ bias, const float* __restrict__ rown,
             float* __restrict__ C, __nv_bfloat16* __restrict__ Dh,
             __nv_bfloat16* __restrict__ Dl, int M, int N, int K) {
    __shared__ __align__(16) float As[2][BK][BM];
    __shared__ __align__(16) float Bs[2][BK][BN];
    const int tid = threadIdx.x;
    const int tx = tid & 15, ty = tid >> 4;
    const int m0 = blockIdx.y * BM, n0 = blockIdx.x * BN;
    const int arow = tid >> 1, akq = (tid & 1) * 4;
    const float* Aptr = A + (size_t)(m0 + arow) * K + akq;
    const int brow = tid >> 5, bcol = (tid & 31) * 4;
    const float* Bptr = B + (size_t)brow * N + n0 + bcol;
    float acc[8][8];
#pragma unroll
    for (int i = 0; i < 8; i++)
#pragma unroll
        for (int j = 0; j < 8; j++) acc[i][j] = 0.f;
    const int nt = K / BK;
    float4 a4 = *(const float4*)(Aptr);
    float4 b4 = *(const float4*)(Bptr);
    As[0][akq + 0][arow] = a4.x; As[0][akq + 1][arow] = a4.y;
    As[0][akq + 2][arow] = a4.z; As[0][akq + 3][arow] = a4.w;
    *(float4*)&Bs[0][brow][bcol] = b4;
    __syncthreads();
    int cur = 0;
    for (int t = 0; t < nt; t++) {
        if (t + 1 < nt) {
            a4 = *(const float4*)(Aptr + (t + 1) * BK);
            b4 = *(const float4*)(Bptr + (size_t)(t + 1) * BK * N);
        }
#pragma unroll
        for (int kk = 0; kk < BK; kk++) {
            float4 a0 = *(const float4*)&As[cur][kk][ty * 4];
            float4 a1 = *(const float4*)&As[cur][kk][64 + ty * 4];
            float4 b0 = *(const float4*)&Bs[cur][kk][tx * 4];
            float4 b1 = *(const float4*)&Bs[cur][kk][64 + tx * 4];
            float ar[8] = {a0.x, a0.y, a0.z, a0.w, a1.x, a1.y, a1.z, a1.w};
            float br[8] = {b0.x, b0.y, b0.z, b0.w, b1.x, b1.y, b1.z, b1.w};
#pragma unroll
            for (int i = 0; i < 8; i++)
#pragma unroll
                for (int j = 0; j < 8; j++) acc[i][j] = fmaf(ar[i], br[j], acc[i][j]);
        }
        if (t + 1 < nt) {
            int nx = cur ^ 1;
            As[nx][akq + 0][arow] = a4.x; As[nx][akq + 1][arow] = a4.y;
            As[nx][akq + 2][arow] = a4.z; As[nx][akq + 3][arow] = a4.w;
            *(float4*)&Bs[nx][brow][bcol] = b4;
        }
        __syncthreads();
        cur ^= 1;
    }
#pragma unroll
    for (int i = 0; i < 8; i++) {
        int r = m0 + ((i < 4) ? (ty * 4 + i) : (64 + ty * 4 + (i - 4)));
        float rn = (EPI == 2) ? rown[r] : 0.f;
#pragma unroll
        for (int jh = 0; jh < 2; jh++) {
            int c = n0 + jh * 64 + tx * 4;
            float4 bv = *(const float4*)(bias + c);
            const float* ap = &acc[i][jh * 4];
            float4 v;
            if (EPI == 2) {
                v.x = rn + bv.x - 2.f * ap[0];
                v.y = rn + bv.y - 2.f * ap[1];
                v.z = rn + bv.z - 2.f * ap[2];
                v.w = rn + bv.w - 2.f * ap[3];
            } else {
                v.x = ap[0] + bv.x; v.y = ap[1] + bv.y;
                v.z = ap[2] + bv.z; v.w = ap[3] + bv.w;
                if (EPI == 1) {
                    v.x = tanhf(v.x); v.y = tanhf(v.y);
                    v.z = tanhf(v.z); v.w = tanhf(v.w);
                }
            }
            *(float4*)(C + (size_t)r * N + c) = v;
            if (EPI == 2) {
                __nv_bfloat16 h0, l0, h1, l1, h2, l2, h3, l3;
                split2(v.x, h0, l0); split2(v.y, h1, l1);
                split2(v.z, h2, l2); split2(v.w, h3, l3);
                __nv_bfloat162 ph0, ph1, pl0, pl1;
                ph0.x = h0; ph0.y = h1; ph1.x = h2; ph1.y = h3;
                pl0.x = l0; pl0.y = l1; pl1.x = l2; pl1.y = l3;
                size_t off = (size_t)r * N + c;
                *(__nv_bfloat162*)(Dh + off) = ph0;
                *(__nv_bfloat162*)(Dh + off + 2) = ph1;
                *(__nv_bfloat162*)(Dl + off) = pl0;
                *(__nv_bfloat162*)(Dl + off + 2) = pl1;
            }
        }
    }
}

// ---------------- small kernels --------------------------------------------------------
__global__ void prep_codebook_kernel(const float* __restrict__ cb) {
    int k = blockIdx.x;
    float s = 0.f;
    for (int d = threadIdx.x; d < OBS; d += blockDim.x) {
        float v = cb[(size_t)k * OBS + d];
        g_cbT[(size_t)d * KCB + k] = v;
        s += v * v;
    }
    s = blockReduceSum(s);
    if (threadIdx.x == 0) g_cnorm[k] = s;
}

__global__ void rownorm_kernel(const float* __restrict__ x, float* __restrict__ out, int D) {
    int b = blockIdx.x;
    const float* r = x + (size_t)b * D;
    float s = 0.f;
    for (int d = threadIdx.x; d < D; d += blockDim.x) {
        float v = r[d];
        s += v * v;
    }
    s = blockReduceSum(s);
    if (threadIdx.x == 0) out[b] = s;
}

__global__ void argmin_kernel(const float* __restrict__ dist, float* __restrict__ prop_out_f) {
    __shared__ float sv[256];
    __shared__ int si[256];
    int b = blockIdx.x;
    const float* r = dist + (size_t)b * KCB;
    float best = INFINITY;
    int bi = KCB;
    for (int k = threadIdx.x; k < KCB; k += 256) {
        float v = r[k];
        if (v < best) { best = v; bi = k; }
    }
    sv[threadIdx.x] = best;
    si[threadIdx.x] = bi;
    __syncthreads();
    for (int s = 128; s > 0; s >>= 1) {
        if (threadIdx.x < s) {
            float ov = sv[threadIdx.x + s];
            int oi = si[threadIdx.x + s];
            if (ov < sv[threadIdx.x] || (ov == sv[threadIdx.x] && oi < si[threadIdx.x])) {
                sv[threadIdx.x] = ov;
                si[threadIdx.x] = oi;
            }
        }
        __syncthreads();
    }
    if (threadIdx.x == 0) {
        g_prop[b] = si[0];
        prop_out_f[b] = (float)si[0];
    }
}

__global__ void xsplit_kernel(const float* __restrict__ X, __nv_bfloat16* __restrict__ xh,
                              __nv_bfloat16* __restrict__ xl) {
    size_t i = (size_t)blockIdx.x * blockDim.x + threadIdx.x;  // B*1024
    float v = X[i];
    __nv_bfloat16 h, l;
    split2(v, h, l);
    xh[i] = h;
    xl[i] = l;
}

// loss: gathers recon and quantized from the 512-row decoder/codebook tables
__global__ void loss_partial_kernel(const float* __restrict__ dx, const float* __restrict__ cb) {
    const size_t NTOT = (size_t)BSZ * OBS;
    float s1 = 0.f, s2 = 0.f;
    for (size_t i = (size_t)blockIdx.x * blockDim.x + threadIdx.x; i < NTOT;
         i += (size_t)gridDim.x * blockDim.x) {
        int b = (int)(i >> 10);
        int d = (int)(i & 1023);
        size_t ko = (size_t)g_prop[b] * OBS + d;
        float a = dx[i] - g_cb_recon[ko];
        s1 += a * a;
        float c = g_enc[i] - cb[ko];
        s2 += c * c;
    }
    s1 = blockReduceSum(s1);
    __syncthreads();
    s2 = blockReduceSum(s2);
    if (threadIdx.x == 0) {
        g_part[2 * blockIdx.x + 0] = s1;
        g_part[2 * blockIdx.x + 1] = s2;
    }
}

__global__ void finalize_total_kernel(int nb, float* __restrict__ out_total) {
    float s1 = 0.f, s2 = 0.f;
    for (int i = threadIdx.x; i < nb; i += 256) {
        s1 += g_part[2 * i + 0];
        s2 += g_part[2 * i + 1];
    }
    s1 = blockReduceSum(s1);
    __syncthreads();
    s2 = blockReduceSum(s2);
    if (threadIdx.x == 0) {
        const float inv = 1.f / ((float)BSZ * (float)OBS);
        float tot = s1 * inv + 2.f * (s2 * inv);
        g_total[0] = tot;
        out_total[0] = tot;
    }
}

__global__ void policy_kernel(const float* __restrict__ A_, const float* __restrict__ log_std,
                              float* __restrict__ out_loss, float* __restrict__ out_losspi) {
    int b = blockIdx.x;
    int j = threadIdx.x;
    float ls = log_std[j];
    float sd = expf(ls);
    float z = (A_[(size_t)b * OUTD + j] - g_mu[(size_t)b * OUTD + j]) / sd;
    float logp = -0.5f * z * z - ls - 0.5f * LOG2PI_F;
    float term = 1.f / (expf(logp) + 0.1f);
    float lp = blockReduceSum(term);
    if (threadIdx.x == 0) {
        out_losspi[b] = lp;
        out_loss[b] = lp * g_total[0];
    }
}

// ---------------- launch ----------------------------------------------------------------
static inline dim3 ggrid(int M, int N) { return dim3(N / 128, M / 128); }

extern "C" void kernel_launch(void* const* d_in, const int* in_sizes, int n_in,
                              void* d_out, int out_size) {
    const float* X        = (const float*)d_in[0];
    const float* Delta_X  = (const float*)d_in[1];
    const float* A        = (const float*)d_in[2];
    const float* enc_w1   = (const float*)d_in[3];
    const float* enc_b1   = (const float*)d_in[4];
    const float* enc_w2   = (const float*)d_in[5];
    const float* enc_b2   = (const float*)d_in[6];
    const float* prenet_w = (const float*)d_in[7];
    const float* prenet_b = (const float*)d_in[8];
    const float* codebook = (const float*)d_in[9];
    const float* postnet_w= (const float*)d_in[10];
    const float* postnet_b= (const float*)d_in[11];
    const float* dec_w1   = (const float*)d_in[12];
    const float* dec_b1   = (const float*)d_in[13];
    const float* dec_w2   = (const float*)d_in[14];
    const float* dec_b2   = (const float*)d_in[15];
    const float* dec_w3   = (const float*)d_in[16];
    const float* dec_b3   = (const float*)d_in[17];
    const float* act_w1   = (const float*)d_in[18];
    const float* act_b1   = (const float*)d_in[19];
    const float* act_w2   = (const float*)d_in[20];
    const float* act_b2   = (const float*)d_in[21];
    const float* act_w3   = (const float*)d_in[22];
    const float* act_b3   = (const float*)d_in[23];
    const float* log_std  = (const float*)d_in[24];

    float* out = (float*)d_out;
    float* out_loss   = out;
    float* out_losspi = out + BSZ;
    float* out_X      = out + 2 * (size_t)BSZ;
    float* out_prop   = out + 2 * (size_t)BSZ + (size_t)BSZ * OBS;
    float* out_total  = out_prop + BSZ;

    float *p_h1, *p_h2, *p_enc, *p_dist, *p_mu, *p_cbT, *p_cnorm, *p_xnorm, *p_zb, *p_p1;
    float *p_d0, *p_d1, *p_d2, *p_rec;
    __nv_bfloat16 *p_wh, *p_wl, *p_xh, *p_xl, *p_dh, *p_dl, *p_a1h, *p_a1l, *p_a2h, *p_a2l;
    cudaGetSymbolAddress((void**)&p_h1, g_h1);
    cudaGetSymbolAddress((void**)&p_h2, g_h2);
    cudaGetSymbolAddress((void**)&p_enc, g_enc);
    cudaGetSymbolAddress((void**)&p_dist, g_dist);
    cudaGetSymbolAddress((void**)&p_mu, g_mu);
    cudaGetSymbolAddress((void**)&p_cbT, g_cbT);
    cudaGetSymbolAddress((void**)&p_cnorm, g_cnorm);
    cudaGetSymbolAddress((void**)&p_xnorm, g_xnorm);
    cudaGetSymbolAddress((void**)&p_zb, g_zb);
    cudaGetSymbolAddress((void**)&p_p1, g_p1);
    cudaGetSymbolAddress((void**)&p_d0, g_cb_d0);
    cudaGetSymbolAddress((void**)&p_d1, g_cb_d1);
    cudaGetSymbolAddress((void**)&p_d2, g_cb_d2);
    cudaGetSymbolAddress((void**)&p_rec, g_cb_recon);
    cudaGetSymbolAddress((void**)&p_wh, g_wt_hi);
    cudaGetSymbolAddress((void**)&p_wl, g_wt_lo);
    cudaGetSymbolAddress((void**)&p_xh, g_xs_hi);
    cudaGetSymbolAddress((void**)&p_xl, g_xs_lo);
    cudaGetSymbolAddress((void**)&p_dh, g_ds_hi);
    cudaGetSymbolAddress((void**)&p_dl, g_ds_lo);
    cudaGetSymbolAddress((void**)&p_a1h, g_a1_hi);
    cudaGetSymbolAddress((void**)&p_a1l, g_a1_lo);
    cudaGetSymbolAddress((void**)&p_a2h, g_a2_hi);
    cudaGetSymbolAddress((void**)&p_a2l, g_a2_lo);

    cudaFuncSetAttribute(mma_gemm<0, 1, 0, 0>, cudaFuncAttributeMaxDynamicSharedMemorySize, GEMM_SMEM);
    cudaFuncSetAttribute(mma_gemm<1, 0, 1, 1>, cudaFuncAttributeMaxDynamicSharedMemorySize, GEMM_SMEM);
    cudaFuncSetAttribute(mma_gemm<1, 0, 1, 0>, cudaFuncAttributeMaxDynamicSharedMemorySize, GEMM_SMEM);

    // ---- second stream + events (created once, first call is non-capturing) ----
    static cudaStream_t s2 = nullptr;
    static cudaEvent_t evRoot = nullptr, evS2 = nullptr, evArg = nullptr, evTot = nullptr;
    if (s2 == nullptr) {
        cudaStreamCreateWithFlags(&s2, cudaStreamNonBlocking);
        cudaEventCreateWithFlags(&evRoot, cudaEventDisableTiming);
        cudaEventCreateWithFlags(&evS2, cudaEventDisableTiming);
        cudaEventCreateWithFlags(&evArg, cudaEventDisableTiming);
        cudaEventCreateWithFlags(&evTot, cudaEventDisableTiming);
    }

    dim3 tb(32, 8);

    // fork s2 off the main stream
    cudaEventRecord(evRoot, 0);
    cudaStreamWaitEvent(s2, evRoot, 0);

    // ---------- s2 branch: X split, actor weight prep, decoder-512, act1 X-part ----------
    xsplit_kernel<<<(BSZ * OBS) / 256, 256, 0, s2>>>(X, p_xh, p_xl);
    wsplit_kernel<<<dim3(2048 / 32, 1024 / 32), tb, 0, s2>>>(act_w1, p_wh + O_A1X, p_wl + O_A1X, 1024, 2048);
    wsplit_kernel<<<dim3(2048 / 32, 512 / 32), tb, 0, s2>>>(act_w1 + (size_t)1024 * 2048,
                                                            p_wh + O_A1D, p_wl + O_A1D, 512, 2048);
    wsplit_kernel<<<dim3(2048 / 32, 2048 / 32), tb, 0, s2>>>(act_w2, p_wh + O_ACT2, p_wl + O_ACT2, 2048, 2048);
    wsplit_kernel<<<dim3(256 / 32, 2048 / 32), tb, 0, s2>>>(act_w3, p_wh + O_ACT3, p_wl + O_ACT3, 2048, 256);
    // decoder on 512 unique codebook rows (exact fp32)
    sgemm_kernel<1><<<dim3(1024 / BN, KCB / BM), 256, 0, s2>>>(codebook, postnet_w, postnet_b, nullptr, p_d0, nullptr, nullptr, KCB, 1024, 1024);
    sgemm_kernel<1><<<dim3(2048 / BN, KCB / BM), 256, 0, s2>>>(p_d0, dec_w1, dec_b1, nullptr, p_d1, nullptr, nullptr, KCB, 2048, 1024);
    sgemm_kernel<1><<<dim3(2048 / BN, KCB / BM), 256, 0, s2>>>(p_d1, dec_w2, dec_b2, nullptr, p_d2, nullptr, nullptr, KCB, 2048, 2048);
    sgemm_kernel<0><<<dim3(1024 / BN, KCB / BM), 256, 0, s2>>>(p_d2, dec_w3, dec_b3, nullptr, p_rec, nullptr, nullptr, KCB, 1024, 2048);
    // act1 X-part: fp32 partial (zero bias), overlaps the fp32 encoder on the tensor pipe
    mma_gemm<0, 1, 0, 0><<<ggrid(BSZ, 2048), 256, GEMM_SMEM, s2>>>(
        p_xh, p_xl, p_wh + O_A1X, p_wl + O_A1X, p_zb, nullptr,
        p_p1, nullptr, nullptr, BSZ, 2048, 1024);
    cudaMemcpyAsync(out_X, X, (size_t)BSZ * OBS * sizeof(float), cudaMemcpyDeviceToDevice, s2);
    cudaEventRecord(evS2, s2);

    // ---------- main stream: encoder chain (fp32 FFMA) + distances + argmin ----------
    prep_codebook_kernel<<<KCB, 256>>>(codebook);
    sgemm_kernel<1><<<dim3(512 / BN, BSZ / BM), 256>>>(Delta_X, enc_w1, enc_b1, nullptr, p_h1, nullptr, nullptr, BSZ, 512, 1024);
    sgemm_kernel<1><<<dim3(1024 / BN, BSZ / BM), 256>>>(p_h1, enc_w2, enc_b2, nullptr, p_h2, nullptr, nullptr, BSZ, 1024, 512);
    sgemm_kernel<0><<<dim3(1024 / BN, BSZ / BM), 256>>>(p_h2, prenet_w, prenet_b, nullptr, p_enc, nullptr, nullptr, BSZ, 1024, 1024);
    rownorm_kernel<<<BSZ, 256>>>(p_enc, p_xnorm, OBS);
    sgemm_kernel<2><<<dim3(KCB / BN, BSZ / BM), 256>>>(p_enc, p_cbT, p_cnorm, p_xnorm, p_dist, p_dh, p_dl, BSZ, KCB, OBS);
    argmin_kernel<<<BSZ, 256>>>(p_dist, out_prop);
    cudaEventRecord(evArg, 0);

    // ---------- s2: VQ losses (overlap with actor GEMMs on main stream) ----------
    cudaStreamWaitEvent(s2, evArg, 0);
    loss_partial_kernel<<<2048, 256, 0, s2>>>(Delta_X, codebook);
    finalize_total_kernel<<<1, 256, 0, s2>>>(2048, out_total);
    cudaEventRecord(evTot, s2);

    // ---------- main stream: actor dist-part + act2 + act3 ----------
    cudaStreamWaitEvent(0, evS2, 0);
    mma_gemm<1, 0, 1, 1><<<ggrid(BSZ, 2048), 256, GEMM_SMEM>>>(
        p_dh, p_dl, p_wh + O_A1D, p_wl + O_A1D, act_b1, p_p1,
        nullptr, p_a1h, p_a1l, BSZ, 2048, 512);
    mma_gemm<1, 0, 1, 0><<<ggrid(BSZ, 2048), 256, GEMM_SMEM>>>(
        p_a1h, p_a1l, p_wh + O_ACT2, p_wl + O_ACT2, act_b2, nullptr,
        nullptr, p_a2h, p_a2l, BSZ, 2048, 2048);
    mma_gemm<0, 1, 0, 0><<<ggrid(BSZ, 256), 256, GEMM_SMEM>>>(
        p_a2h, p_a2l, p_wh + O_ACT3, p_wl + O_ACT3, act_b3, nullptr,
        p_mu, nullptr, nullptr, BSZ, 256, 2048);

    // ---------- join and finish ----------
    cudaStreamWaitEvent(0, evTot, 0);
    policy_kernel<<<BSZ, 256>>>(A, log_std, out_loss, out_losspi);
}